// round 3
// baseline (speedup 1.0000x reference)
#include <cuda_runtime.h>
#include <math.h>
#include <stdint.h>

#define S_LEN 2048
#define HID   256
#define BN    16
#define M_ROWS (BN * S_LEN)   // 32768

// Scratch (device globals: no allocation allowed in kernel_launch)
__device__ float  g_Q[(size_t)M_ROWS * HID];
__device__ float  g_K[(size_t)M_ROWS * HID];
__device__ float  g_V[(size_t)M_ROWS * HID];
__device__ float4 g_tab[S_LEN * 128];   // {sin, cos, scale, 1/scale} per (pos, halfdim)

// ---------------------------------------------------------------------------
// xpos table: sin/cos/scale per (position s, half-dim i)
// ---------------------------------------------------------------------------
__global__ void tab_kernel() {
    int idx = blockIdx.x * 256 + threadIdx.x;
    if (idx >= S_LEN * 128) return;
    int s = idx >> 7;
    int i = idx & 127;
    // inv_freq = 10000^(-i/128) = exp2(-i * log2(10000)/128), double (phase-sensitive)
    float inv_freq = (float)exp2(-(double)i * (13.287712379549449 / 128.0));
    float theta = (float)s * inv_freq;
    float sn, cs;
    sincosf(theta, &sn, &cs);
    float base  = ((float)(2 * i) + 102.4f) / 358.4f;   // (2i + 0.4*H)/(1.4*H)
    float scale = exp2f(log2f(base) * ((float)s * (1.0f / 512.0f)));
    g_tab[idx] = make_float4(sn, cs, scale, 1.0f / scale);
}

// ---------------------------------------------------------------------------
// Fused QKV projection + xpos epilogue.
// grid: (HID/64, M_ROWS/64, 3)  z: 0=Q (xpos), 1=K (xpos downscale), 2=V
// block: 16x16, each thread computes a 4x4 micro-tile.
// ---------------------------------------------------------------------------
__global__ void __launch_bounds__(256) proj_kernel(
                            const float* __restrict__ X,
                            const float* __restrict__ Wq,
                            const float* __restrict__ Wk,
                            const float* __restrict__ Wv) {
    int mode = blockIdx.z;
    const float* W = (mode == 0) ? Wq : (mode == 1) ? Wk : Wv;
    float* outp = (mode == 0) ? g_Q : (mode == 1) ? g_K : g_V;

    int row0 = blockIdx.y * 64;
    int col0 = blockIdx.x * 64;

    __shared__ float As[64][33];   // [m][k], padded
    __shared__ float Bs[32][64];   // [k][n]

    int tx = threadIdx.x, ty = threadIdx.y;
    int tid = ty * 16 + tx;

    float acc[4][4];
#pragma unroll
    for (int i = 0; i < 4; i++)
#pragma unroll
        for (int j = 0; j < 4; j++) acc[i][j] = 0.f;

    int kk = tid & 31;
    int rbase = tid >> 5;          // 0..7
    int nn = tid & 63;
    int kb = tid >> 6;             // 0..3

    for (int k0 = 0; k0 < HID; k0 += 32) {
#pragma unroll
        for (int i = 0; i < 8; i++) {
            int r = rbase + i * 8;
            As[r][kk] = X[(size_t)(row0 + r) * HID + k0 + kk];
        }
#pragma unroll
        for (int i = 0; i < 8; i++) {
            int k = kb + i * 4;
            Bs[k][nn] = W[(size_t)(k0 + k) * HID + col0 + nn];
        }
        __syncthreads();
#pragma unroll
        for (int k2 = 0; k2 < 32; k2++) {
            float a0 = As[ty * 4 + 0][k2];
            float a1 = As[ty * 4 + 1][k2];
            float a2 = As[ty * 4 + 2][k2];
            float a3 = As[ty * 4 + 3][k2];
            float4 b = ((const float4*)&Bs[k2][0])[tx];
            acc[0][0] += a0 * b.x; acc[0][1] += a0 * b.y; acc[0][2] += a0 * b.z; acc[0][3] += a0 * b.w;
            acc[1][0] += a1 * b.x; acc[1][1] += a1 * b.y; acc[1][2] += a1 * b.z; acc[1][3] += a1 * b.w;
            acc[2][0] += a2 * b.x; acc[2][1] += a2 * b.y; acc[2][2] += a2 * b.z; acc[2][3] += a2 * b.w;
            acc[3][0] += a3 * b.x; acc[3][1] += a3 * b.y; acc[3][2] += a3 * b.z; acc[3][3] += a3 * b.w;
        }
        __syncthreads();
    }

    int col = col0 + tx * 4;
#pragma unroll
    for (int i = 0; i < 4; i++) {
        int gr = row0 + ty * 4 + i;
        float4 r;
        if (mode == 2) {
            r = make_float4(acc[i][0], acc[i][1], acc[i][2], acc[i][3]);
        } else {
            int s = gr & (S_LEN - 1);
            float4 t0 = g_tab[s * 128 + (col >> 1)];
            float4 t1 = g_tab[s * 128 + (col >> 1) + 1];
            float sc0 = (mode == 0) ? t0.z : t0.w;
            float sc1 = (mode == 0) ? t1.z : t1.w;
            float sn0 = t0.x * sc0, cs0 = t0.y * sc0;
            float sn1 = t1.x * sc1, cs1 = t1.y * sc1;
            r.x = acc[i][0] * cs0 - acc[i][1] * sn0;
            r.y = acc[i][1] * cs0 + acc[i][0] * sn0;
            r.z = acc[i][2] * cs1 - acc[i][3] * sn1;
            r.w = acc[i][3] * cs1 + acc[i][2] * sn1;
        }
        ((float4*)(outp + (size_t)gr * HID))[col >> 2] = r;
    }
}

// ---------------------------------------------------------------------------
// Flash-style retention attention, bank-conflict-free smem mapping.
// grid: (S/32 q-tiles, BN). block 256 threads. 2 CTAs/SM (~101 KB dyn smem).
// Q/K smem rows padded to 65 float4 (260 floats) so lanes sweep all bank
// groups; micro-tile columns are {c, c+16} (lane-consecutive), PV columns are
// {l, l+16, l+32, l+48} float4 chunks (lane-consecutive within a V row).
// ---------------------------------------------------------------------------
#define L2G  (-0.045803586f)   // log2(0.96875)
#define QK_STR4 65              // padded row stride in float4

__global__ void __launch_bounds__(256, 2) attn_kernel(float* __restrict__ out) {
    extern __shared__ float sm[];
    float4* Qs4 = (float4*)sm;                         // 32 x 65 float4
    float4* Ks4 = Qs4 + 32 * QK_STR4;                  // 32 x 65 float4
    float4* Vs4 = Ks4 + 32 * QK_STR4;                  // 32 x 64 float4
    float*  Ps  = (float*)(Vs4 + 32 * 64);             // 32 x 33 floats

    int qt = gridDim.x - 1 - blockIdx.x;   // heavy blocks launch first
    int bn = blockIdx.y;
    int t  = threadIdx.x;
    int q0 = qt * 32;

    int R = t >> 4;        // S rows {R, R+16}
    int C = t & 15;        // S cols {C, C+16}; PV col chunks {C, C+16, C+32, C+48} (float4)

    // load Q tile (padded rows)
    {
        const float4* Qg = (const float4*)(g_Q + ((size_t)bn * S_LEN + q0) * HID);
#pragma unroll
        for (int i = 0; i < 8; i++) {
            int idx = t + i * 256;
            Qs4[(idx >> 6) * QK_STR4 + (idx & 63)] = Qg[idx];
        }
    }

    float o[2][16];
#pragma unroll
    for (int i = 0; i < 2; i++)
#pragma unroll
        for (int j = 0; j < 16; j++) o[i][j] = 0.f;

    for (int kt = 0; kt <= qt; kt++) {
        int j0 = kt * 32;
        __syncthreads();   // prior PV reads done (and Q tile visible on first iter)
        {
            const float4* Kg = (const float4*)(g_K + ((size_t)bn * S_LEN + j0) * HID);
            const float4* Vg = (const float4*)(g_V + ((size_t)bn * S_LEN + j0) * HID);
#pragma unroll
            for (int i = 0; i < 8; i++) {
                int idx = t + i * 256;
                Ks4[(idx >> 6) * QK_STR4 + (idx & 63)] = Kg[idx];
                Vs4[idx] = Vg[idx];
            }
        }
        __syncthreads();

        // --- S = Q K^T (2x2 micro-tile over k=256) ---
        float s00 = 0.f, s01 = 0.f, s10 = 0.f, s11 = 0.f;
        const float4* qa4 = Qs4 + (R +  0) * QK_STR4;
        const float4* qb4 = Qs4 + (R + 16) * QK_STR4;
        const float4* ka4 = Ks4 + (C +  0) * QK_STR4;
        const float4* kb4 = Ks4 + (C + 16) * QK_STR4;
#pragma unroll 8
        for (int k4 = 0; k4 < 64; k4++) {
            float4 qa = qa4[k4];
            float4 qb = qb4[k4];
            float4 ka = ka4[k4];
            float4 kb = kb4[k4];
            s00 += qa.x * ka.x + qa.y * ka.y + qa.z * ka.z + qa.w * ka.w;
            s01 += qa.x * kb.x + qa.y * kb.y + qa.z * kb.z + qa.w * kb.w;
            s10 += qb.x * ka.x + qb.y * ka.y + qb.z * ka.z + qb.w * ka.w;
            s11 += qb.x * kb.x + qb.y * kb.y + qb.z * kb.z + qb.w * kb.w;
        }

        // --- decay + causal mask ---
        // element diffs: (R,C)=dA, (R,C+16)=dA-16, (R+16,C)=dA+16, (R+16,C+16)=dA
        int dA = (q0 + R) - (j0 + C);
        float eA = exp2f((float)dA        * L2G);
        float eM = exp2f((float)(dA - 16) * L2G);
        float eP = exp2f((float)(dA + 16) * L2G);
        Ps[(R +  0) * 33 + C +  0] = (dA >=   0) ? s00 * eA : 0.f;
        Ps[(R +  0) * 33 + C + 16] = (dA >=  16) ? s01 * eM : 0.f;
        Ps[(R + 16) * 33 + C +  0] = (dA >= -16) ? s10 * eP : 0.f;
        Ps[(R + 16) * 33 + C + 16] = (dA >=   0) ? s11 * eA : 0.f;

        __syncthreads();

        // --- O += P V (2 rows x 16 cols per thread, lane-consecutive chunks) ---
#pragma unroll 8
        for (int j = 0; j < 32; j++) {
            float p0 = Ps[(R +  0) * 33 + j];
            float p1 = Ps[(R + 16) * 33 + j];
            const float4* vr = Vs4 + j * 64;
#pragma unroll
            for (int q = 0; q < 4; q++) {
                float4 v = vr[C + 16 * q];
                o[0][q * 4 + 0] += p0 * v.x; o[0][q * 4 + 1] += p0 * v.y;
                o[0][q * 4 + 2] += p0 * v.z; o[0][q * 4 + 3] += p0 * v.w;
                o[1][q * 4 + 0] += p1 * v.x; o[1][q * 4 + 1] += p1 * v.y;
                o[1][q * 4 + 2] += p1 * v.z; o[1][q * 4 + 3] += p1 * v.w;
            }
        }
    }

    // write output
    float4* Og = (float4*)(out + ((size_t)bn * S_LEN + q0) * HID);
#pragma unroll
    for (int i = 0; i < 2; i++) {
        int row = R + i * 16;
#pragma unroll
        for (int q = 0; q < 4; q++) {
            float4 v = make_float4(o[i][q * 4 + 0], o[i][q * 4 + 1],
                                   o[i][q * 4 + 2], o[i][q * 4 + 3]);
            Og[row * 64 + C + 16 * q] = v;
        }
    }
}

// ---------------------------------------------------------------------------
extern "C" void kernel_launch(void* const* d_in, const int* in_sizes, int n_in,
                              void* d_out, int out_size) {
    const float* X  = (const float*)d_in[0];
    const float* Wq = (const float*)d_in[1];
    const float* Wk = (const float*)d_in[2];
    const float* Wv = (const float*)d_in[3];
    float* out = (float*)d_out;

    // 1) xpos table
    tab_kernel<<<(S_LEN * 128 + 255) / 256, 256>>>();

    // 2) fused QKV projection + xpos
    dim3 pgrid(HID / 64, M_ROWS / 64, 3);
    proj_kernel<<<pgrid, dim3(16, 16)>>>(X, Wq, Wk, Wv);

    // 3) retention attention
    int smem = (32 * QK_STR4 * 4 * 2 + 32 * 64 * 4 + 32 * 33) * (int)sizeof(float);
    cudaFuncSetAttribute(attn_kernel, cudaFuncAttributeMaxDynamicSharedMemorySize, smem);
    attn_kernel<<<dim3(S_LEN / 32, BN), 256, smem>>>(out);
}

// round 5
// speedup vs baseline: 1.4644x; 1.4644x over previous
#include <cuda_runtime.h>
#include <cuda_bf16.h>
#include <mma.h>
#include <math.h>
#include <stdint.h>

using namespace nvcuda;

#define S_LEN 2048
#define HID   256
#define BN    16
#define M_ROWS (BN * S_LEN)   // 32768

#define L2G  (-0.04580369f)           // log2(0.96875)
#define IGAM (1.03225806451612903f)   // 1/0.96875

// ---------------------------------------------------------------------------
// Device-global scratch (bf16 hi/lo split of Q, K, V)
// ---------------------------------------------------------------------------
__device__ __align__(256) __nv_bfloat16 g_Qh[(size_t)M_ROWS * HID];
__device__ __align__(256) __nv_bfloat16 g_Ql[(size_t)M_ROWS * HID];
__device__ __align__(256) __nv_bfloat16 g_Kh[(size_t)M_ROWS * HID];
__device__ __align__(256) __nv_bfloat16 g_Kl[(size_t)M_ROWS * HID];
__device__ __align__(256) __nv_bfloat16 g_Vh[(size_t)M_ROWS * HID];
__device__ __align__(256) __nv_bfloat16 g_Vl[(size_t)M_ROWS * HID];
__device__ float4 g_tab[S_LEN * 128];   // {sin, cos, scale, 1/scale}

// ---------------------------------------------------------------------------
// helpers
// ---------------------------------------------------------------------------
__device__ __forceinline__ uint32_t smem_u32(const void* p) {
    uint32_t a;
    asm("{ .reg .u64 t; cvta.to.shared.u64 t, %1; cvt.u32.u64 %0, t; }" : "=r"(a) : "l"(p));
    return a;
}
__device__ __forceinline__ void cpa16(uint32_t dst, const void* src) {
    asm volatile("cp.async.cg.shared.global [%0], [%1], 16;" :: "r"(dst), "l"(src));
}
#define CPA_COMMIT() asm volatile("cp.async.commit_group;" ::: "memory")
#define CPA_WAIT(n)  asm volatile("cp.async.wait_group %0;" :: "n"(n) : "memory")

__device__ __forceinline__ void split2(float a, float b, uint32_t& h, uint32_t& l) {
    __nv_bfloat162 hh = __floats2bfloat162_rn(a, b);
    __nv_bfloat162 ll = __floats2bfloat162_rn(a - __bfloat162float(hh.x),
                                              b - __bfloat162float(hh.y));
    h = *(uint32_t*)&hh;
    l = *(uint32_t*)&ll;
}

// ---------------------------------------------------------------------------
// xpos table
// ---------------------------------------------------------------------------
__global__ void tab_kernel() {
    int idx = blockIdx.x * 256 + threadIdx.x;
    if (idx >= S_LEN * 128) return;
    int s = idx >> 7, i = idx & 127;
    float inv_freq = (float)exp2(-(double)i * (13.287712379549449 / 128.0));
    float sn, cs;
    sincosf((float)s * inv_freq, &sn, &cs);
    float base  = ((float)(2 * i) + 102.4f) / 358.4f;
    float scale = exp2f(log2f(base) * ((float)s * (1.0f / 512.0f)));
    g_tab[idx] = make_float4(sn, cs, scale, 1.0f / scale);
}

// ---------------------------------------------------------------------------
// Fused QKV projection + xpos + bf16 hi/lo split epilogue (SIMT fp32 GEMM)
// grid: (HID/64, M_ROWS/64, 3)  z: 0=Q (xpos), 1=K (xpos downscale), 2=V
// ---------------------------------------------------------------------------
__global__ void __launch_bounds__(256) proj_kernel(
        const float* __restrict__ X, const float* __restrict__ Wq,
        const float* __restrict__ Wk, const float* __restrict__ Wv) {
    int mode = blockIdx.z;
    const float* W = (mode == 0) ? Wq : (mode == 1) ? Wk : Wv;

    int row0 = blockIdx.y * 64;
    int col0 = blockIdx.x * 64;

    __shared__ float As[64][33];
    __shared__ float Bs[32][64];

    int tx = threadIdx.x, ty = threadIdx.y;
    int tid = ty * 16 + tx;
    float acc[4][4];
#pragma unroll
    for (int i = 0; i < 4; i++)
#pragma unroll
        for (int j = 0; j < 4; j++) acc[i][j] = 0.f;

    int kk = tid & 31, rbase = tid >> 5, nn = tid & 63, kb = tid >> 6;

    for (int k0 = 0; k0 < HID; k0 += 32) {
#pragma unroll
        for (int i = 0; i < 8; i++)
            As[rbase + i * 8][kk] = X[(size_t)(row0 + rbase + i * 8) * HID + k0 + kk];
#pragma unroll
        for (int i = 0; i < 8; i++)
            Bs[kb + i * 4][nn] = W[(size_t)(k0 + kb + i * 4) * HID + col0 + nn];
        __syncthreads();
#pragma unroll
        for (int k2 = 0; k2 < 32; k2++) {
            float a0 = As[ty * 4 + 0][k2], a1 = As[ty * 4 + 1][k2];
            float a2 = As[ty * 4 + 2][k2], a3 = As[ty * 4 + 3][k2];
            float4 b = ((const float4*)&Bs[k2][0])[tx];
            acc[0][0] += a0 * b.x; acc[0][1] += a0 * b.y; acc[0][2] += a0 * b.z; acc[0][3] += a0 * b.w;
            acc[1][0] += a1 * b.x; acc[1][1] += a1 * b.y; acc[1][2] += a1 * b.z; acc[1][3] += a1 * b.w;
            acc[2][0] += a2 * b.x; acc[2][1] += a2 * b.y; acc[2][2] += a2 * b.z; acc[2][3] += a2 * b.w;
            acc[3][0] += a3 * b.x; acc[3][1] += a3 * b.y; acc[3][2] += a3 * b.z; acc[3][3] += a3 * b.w;
        }
        __syncthreads();
    }

    __nv_bfloat16* oh = (mode == 0) ? g_Qh : (mode == 1) ? g_Kh : g_Vh;
    __nv_bfloat16* ol = (mode == 0) ? g_Ql : (mode == 1) ? g_Kl : g_Vl;
    int col = col0 + tx * 4;
#pragma unroll
    for (int i = 0; i < 4; i++) {
        int gr = row0 + ty * 4 + i;
        float r0, r1, r2, r3;
        if (mode == 2) {
            r0 = acc[i][0]; r1 = acc[i][1]; r2 = acc[i][2]; r3 = acc[i][3];
        } else {
            int s = gr & (S_LEN - 1);
            float4 t0 = g_tab[s * 128 + (col >> 1)];
            float4 t1 = g_tab[s * 128 + (col >> 1) + 1];
            float sc0 = (mode == 0) ? t0.z : t0.w;
            float sc1 = (mode == 0) ? t1.z : t1.w;
            float sn0 = t0.x * sc0, cs0 = t0.y * sc0;
            float sn1 = t1.x * sc1, cs1 = t1.y * sc1;
            r0 = acc[i][0] * cs0 - acc[i][1] * sn0;
            r1 = acc[i][1] * cs0 + acc[i][0] * sn0;
            r2 = acc[i][2] * cs1 - acc[i][3] * sn1;
            r3 = acc[i][3] * cs1 + acc[i][2] * sn1;
        }
        uint2 hw, lw;
        split2(r0, r1, hw.x, lw.x);
        split2(r2, r3, hw.y, lw.y);
        *(uint2*)(oh + (size_t)gr * HID + col) = hw;
        *(uint2*)(ol + (size_t)gr * HID + col) = lw;
    }
}

// ---------------------------------------------------------------------------
// wmma bf16 split-3 retention attention.
// CTA: 128 q-rows × 32-kv tiles, 256 threads (8 warps, 16 rows each).
// Q hi/lo fragments from gmem; K/V hi/lo double-buffered smem (cp.async).
// O accumulated in register fragments across all kv tiles.
// ---------------------------------------------------------------------------
#define LKV 264   // bf16 elems per smem K/V row (256 + 8 pad)
#define LS  36    // f32 S row stride
#define LP  40    // bf16 P row stride

#define SM_KH 0                       // 2 bufs x 32*264*2 = 16896 each
#define SM_KL 33792
#define SM_VH 67584
#define SM_VL 101376
#define SM_SF 135168                  // f32 128*36 = 18432
#define SM_PH 153600                  // bf16 128*40 = 10240
#define SM_PL 163840
#define SM_TOT 174080
#define KVBUF 16896

__global__ void __launch_bounds__(256, 1) attn_kernel(float* __restrict__ out) {
    extern __shared__ __align__(256) char sm[];
    int t = threadIdx.x;
    int wid = t >> 5;

    int bx = blockIdx.x;
    int qt = 15 - (bx >> 4);        // heavy q-tiles first
    int bn = bx & 15;
    int q0 = qt * 128;
    int nkt = 4 * (qt + 1);

    const __nv_bfloat16* Qh = g_Qh + ((size_t)bn * S_LEN + q0) * HID + (size_t)wid * 16 * HID;
    const __nv_bfloat16* Ql = g_Ql + ((size_t)bn * S_LEN + q0) * HID + (size_t)wid * 16 * HID;

    // gmem sources for K/V tiles, smem bases (uint32)
    const __nv_bfloat16* gsrc[4];
    gsrc[0] = g_Kh + ((size_t)bn * S_LEN) * HID;
    gsrc[1] = g_Kl + ((size_t)bn * S_LEN) * HID;
    gsrc[2] = g_Vh + ((size_t)bn * S_LEN) * HID;
    gsrc[3] = g_Vl + ((size_t)bn * S_LEN) * HID;
    uint32_t sb = smem_u32(sm);
    uint32_t sbase[4] = {sb + SM_KH, sb + SM_KL, sb + SM_VH, sb + SM_VL};

    __nv_bfloat16* sKh = (__nv_bfloat16*)(sm + SM_KH);
    __nv_bfloat16* sKl = (__nv_bfloat16*)(sm + SM_KL);
    __nv_bfloat16* sVh = (__nv_bfloat16*)(sm + SM_VH);
    __nv_bfloat16* sVl = (__nv_bfloat16*)(sm + SM_VL);
    float*         sSf = (float*)(sm + SM_SF);
    __nv_bfloat16* sPh = (__nv_bfloat16*)(sm + SM_PH);
    __nv_bfloat16* sPl = (__nv_bfloat16*)(sm + SM_PL);

    // O accumulators: 16 n-tiles of 16x16 per warp
    wmma::fragment<wmma::accumulator, 16, 16, 16, float> oacc[16];
#pragma unroll
    for (int n = 0; n < 16; n++) wmma::fill_fragment(oacc[n], 0.0f);

    // tile loader: 4 arrays x 32 rows x 512B into buffer `buf`
    auto load_kv = [&](int buf, int j0) {
#pragma unroll
        for (int i = 0; i < 16; i++) {
            int arr = i >> 2;
            int rem = t + (i & 3) * 256;
            int row = rem >> 5, c = rem & 31;
            uint32_t dst = sbase[arr] + (uint32_t)buf * KVBUF + row * (LKV * 2) + c * 16;
            const __nv_bfloat16* src = gsrc[arr] + (size_t)(j0 + row) * HID + c * 8;
            cpa16(dst, src);
        }
    };

    load_kv(0, 0);
    CPA_COMMIT();

    for (int kt = 0; kt < nkt; kt++) {
        int j0 = kt * 32;
        int buf = kt & 1;
        if (kt + 1 < nkt) {
            load_kv((kt + 1) & 1, j0 + 32);
            CPA_COMMIT();
            CPA_WAIT(1);
        } else {
            CPA_WAIT(0);
        }
        __syncthreads();

        // ---- S = Q K^T (split-3) ----
        {
            wmma::fragment<wmma::accumulator, 16, 16, 16, float> sacc[2];
            wmma::fill_fragment(sacc[0], 0.0f);
            wmma::fill_fragment(sacc[1], 0.0f);
            const __nv_bfloat16* kh0 = sKh + buf * (KVBUF / 2);
            const __nv_bfloat16* kl0 = sKl + buf * (KVBUF / 2);
#pragma unroll 4
            for (int kc = 0; kc < 16; kc++) {
                wmma::fragment<wmma::matrix_a, 16, 16, 16, __nv_bfloat16, wmma::row_major> ah, al;
                wmma::load_matrix_sync(ah, Qh + kc * 16, HID);
                wmma::load_matrix_sync(al, Ql + kc * 16, HID);
#pragma unroll
                for (int n = 0; n < 2; n++) {
                    wmma::fragment<wmma::matrix_b, 16, 16, 16, __nv_bfloat16, wmma::col_major> bh, bl;
                    wmma::load_matrix_sync(bh, kh0 + n * 16 * LKV + kc * 16, LKV);
                    wmma::load_matrix_sync(bl, kl0 + n * 16 * LKV + kc * 16, LKV);
                    wmma::mma_sync(sacc[n], ah, bh, sacc[n]);
                    wmma::mma_sync(sacc[n], ah, bl, sacc[n]);
                    wmma::mma_sync(sacc[n], al, bh, sacc[n]);
                }
            }
            wmma::store_matrix_sync(sSf + wid * 16 * LS +  0, sacc[0], LS, wmma::mem_row_major);
            wmma::store_matrix_sync(sSf + wid * 16 * LS + 16, sacc[1], LS, wmma::mem_row_major);
        }
        __syncthreads();

        // ---- decay + causal mask + bf16 split -> P ----
        {
            int r = t >> 1;
            int c0 = (t & 1) * 16;
            int d0 = (q0 + r) - (j0 + c0);
            float e = exp2f((float)d0 * L2G);
            const float* srow = sSf + r * LS + c0;
            __nv_bfloat16* ph = sPh + r * LP + c0;
            __nv_bfloat16* pl = sPl + r * LP + c0;
#pragma unroll
            for (int i = 0; i < 16; i++) {
                float p = (i <= d0) ? srow[i] * e : 0.f;
                __nv_bfloat16 h = __float2bfloat16(p);
                ph[i] = h;
                pl[i] = __float2bfloat16(p - __bfloat162float(h));
                e *= IGAM;
            }
        }
        __syncthreads();

        // ---- O += P V (split-3) ----
        {
            const __nv_bfloat16* vh0 = sVh + buf * (KVBUF / 2);
            const __nv_bfloat16* vl0 = sVl + buf * (KVBUF / 2);
#pragma unroll
            for (int jc = 0; jc < 2; jc++) {
                wmma::fragment<wmma::matrix_a, 16, 16, 16, __nv_bfloat16, wmma::row_major> pah, pal;
                wmma::load_matrix_sync(pah, sPh + wid * 16 * LP + jc * 16, LP);
                wmma::load_matrix_sync(pal, sPl + wid * 16 * LP + jc * 16, LP);
#pragma unroll 4
                for (int n = 0; n < 16; n++) {
                    wmma::fragment<wmma::matrix_b, 16, 16, 16, __nv_bfloat16, wmma::row_major> vbh, vbl;
                    wmma::load_matrix_sync(vbh, vh0 + jc * 16 * LKV + n * 16, LKV);
                    wmma::load_matrix_sync(vbl, vl0 + jc * 16 * LKV + n * 16, LKV);
                    wmma::mma_sync(oacc[n], pah, vbh, oacc[n]);
                    wmma::mma_sync(oacc[n], pah, vbl, oacc[n]);
                    wmma::mma_sync(oacc[n], pal, vbh, oacc[n]);
                }
            }
        }
        __syncthreads();
    }

    // ---- store O ----
    float* op = out + ((size_t)bn * S_LEN + q0 + wid * 16) * HID;
#pragma unroll
    for (int n = 0; n < 16; n++)
        wmma::store_matrix_sync(op + n * 16, oacc[n], HID, wmma::mem_row_major);
}

// ---------------------------------------------------------------------------
extern "C" void kernel_launch(void* const* d_in, const int* in_sizes, int n_in,
                              void* d_out, int out_size) {
    const float* X  = (const float*)d_in[0];
    const float* Wq = (const float*)d_in[1];
    const float* Wk = (const float*)d_in[2];
    const float* Wv = (const float*)d_in[3];
    float* out = (float*)d_out;

    tab_kernel<<<(S_LEN * 128 + 255) / 256, 256>>>();

    dim3 pgrid(HID / 64, M_ROWS / 64, 3);
    proj_kernel<<<pgrid, dim3(16, 16)>>>(X, Wq, Wk, Wv);

    cudaFuncSetAttribute(attn_kernel, cudaFuncAttributeMaxDynamicSharedMemorySize, SM_TOT);
    attn_kernel<<<16 * BN, 256, SM_TOT>>>(out);
}

// round 7
// speedup vs baseline: 3.8456x; 2.6261x over previous
#include <cuda_runtime.h>
#include <cuda_bf16.h>
#include <math.h>
#include <stdint.h>

#define S_LEN 2048
#define HID   256
#define BN    16
#define M_ROWS (BN * S_LEN)   // 32768

#define L2G  (-0.04580369f)              // log2(0.96875)
#define IGAM (1.03225806451612903f)      // 1/0.96875
#define G8C  (0.775700596198439598f)     // 0.96875^8 (exact)

// ---------------------------------------------------------------------------
// Device-global scratch (bf16 hi/lo split of Q, K, V)
// ---------------------------------------------------------------------------
__device__ __align__(256) __nv_bfloat16 g_Qh[(size_t)M_ROWS * HID];
__device__ __align__(256) __nv_bfloat16 g_Ql[(size_t)M_ROWS * HID];
__device__ __align__(256) __nv_bfloat16 g_Kh[(size_t)M_ROWS * HID];
__device__ __align__(256) __nv_bfloat16 g_Kl[(size_t)M_ROWS * HID];
__device__ __align__(256) __nv_bfloat16 g_Vh[(size_t)M_ROWS * HID];
__device__ __align__(256) __nv_bfloat16 g_Vl[(size_t)M_ROWS * HID];
__device__ float4 g_tab[S_LEN * 128];   // {sin, cos, scale, 1/scale}

// ---------------------------------------------------------------------------
// helpers
// ---------------------------------------------------------------------------
__device__ __forceinline__ uint32_t smem_u32(const void* p) {
    uint32_t a;
    asm("{ .reg .u64 t; cvta.to.shared.u64 t, %1; cvt.u32.u64 %0, t; }" : "=r"(a) : "l"(p));
    return a;
}
__device__ __forceinline__ void cpa16(uint32_t dst, const void* src) {
    asm volatile("cp.async.cg.shared.global [%0], [%1], 16;" :: "r"(dst), "l"(src));
}
#define CPA_COMMIT() asm volatile("cp.async.commit_group;" ::: "memory")
#define CPA_WAIT(n)  asm volatile("cp.async.wait_group %0;" :: "n"(n) : "memory")

__device__ __forceinline__ void ldsm4(uint32_t* r, uint32_t a) {
    asm volatile("ldmatrix.sync.aligned.m8n8.x4.shared.b16 {%0,%1,%2,%3}, [%4];"
                 : "=r"(r[0]), "=r"(r[1]), "=r"(r[2]), "=r"(r[3]) : "r"(a));
}
__device__ __forceinline__ void ldsm4t(uint32_t* r, uint32_t a) {
    asm volatile("ldmatrix.sync.aligned.m8n8.x4.trans.shared.b16 {%0,%1,%2,%3}, [%4];"
                 : "=r"(r[0]), "=r"(r[1]), "=r"(r[2]), "=r"(r[3]) : "r"(a));
}
__device__ __forceinline__ void mma16816(float* c, const uint32_t* a, const uint32_t* b) {
    asm volatile("mma.sync.aligned.m16n8k16.row.col.f32.bf16.bf16.f32 "
                 "{%0,%1,%2,%3}, {%4,%5,%6,%7}, {%8,%9}, {%0,%1,%2,%3};"
                 : "+f"(c[0]), "+f"(c[1]), "+f"(c[2]), "+f"(c[3])
                 : "r"(a[0]), "r"(a[1]), "r"(a[2]), "r"(a[3]), "r"(b[0]), "r"(b[1]));
}
__device__ __forceinline__ void split2(float a, float b, uint32_t& h, uint32_t& l) {
    __nv_bfloat162 hh = __floats2bfloat162_rn(a, b);
    __nv_bfloat162 ll = __floats2bfloat162_rn(a - __bfloat162float(hh.x),
                                              b - __bfloat162float(hh.y));
    h = *(uint32_t*)&hh;
    l = *(uint32_t*)&ll;
}

// ---------------------------------------------------------------------------
// xpos table
// ---------------------------------------------------------------------------
__global__ void tab_kernel() {
    int idx = blockIdx.x * 256 + threadIdx.x;
    if (idx >= S_LEN * 128) return;
    int s = idx >> 7, i = idx & 127;
    float inv_freq = (float)exp2(-(double)i * (13.287712379549449 / 128.0));
    float sn, cs;
    sincosf((float)s * inv_freq, &sn, &cs);
    float base  = ((float)(2 * i) + 102.4f) / 358.4f;
    float scale = exp2f(log2f(base) * ((float)s * (1.0f / 512.0f)));
    g_tab[idx] = make_float4(sn, cs, scale, 1.0f / scale);
}

// ---------------------------------------------------------------------------
// Fused QKV projection + xpos + bf16 hi/lo split epilogue (SIMT fp32 GEMM)
// ---------------------------------------------------------------------------
__global__ void __launch_bounds__(256) proj_kernel(
        const float* __restrict__ X, const float* __restrict__ Wq,
        const float* __restrict__ Wk, const float* __restrict__ Wv) {
    int mode = blockIdx.z;
    const float* W = (mode == 0) ? Wq : (mode == 1) ? Wk : Wv;

    int row0 = blockIdx.y * 64;
    int col0 = blockIdx.x * 64;

    __shared__ float As[64][33];
    __shared__ float Bs[32][64];

    int tx = threadIdx.x, ty = threadIdx.y;
    int tid = ty * 16 + tx;
    float acc[4][4];
#pragma unroll
    for (int i = 0; i < 4; i++)
#pragma unroll
        for (int j = 0; j < 4; j++) acc[i][j] = 0.f;

    int kk = tid & 31, rbase = tid >> 5, nn = tid & 63, kb = tid >> 6;

    for (int k0 = 0; k0 < HID; k0 += 32) {
#pragma unroll
        for (int i = 0; i < 8; i++)
            As[rbase + i * 8][kk] = X[(size_t)(row0 + rbase + i * 8) * HID + k0 + kk];
#pragma unroll
        for (int i = 0; i < 8; i++)
            Bs[kb + i * 4][nn] = W[(size_t)(k0 + kb + i * 4) * HID + col0 + nn];
        __syncthreads();
#pragma unroll
        for (int k2 = 0; k2 < 32; k2++) {
            float a0 = As[ty * 4 + 0][k2], a1 = As[ty * 4 + 1][k2];
            float a2 = As[ty * 4 + 2][k2], a3 = As[ty * 4 + 3][k2];
            float4 b = ((const float4*)&Bs[k2][0])[tx];
            acc[0][0] += a0 * b.x; acc[0][1] += a0 * b.y; acc[0][2] += a0 * b.z; acc[0][3] += a0 * b.w;
            acc[1][0] += a1 * b.x; acc[1][1] += a1 * b.y; acc[1][2] += a1 * b.z; acc[1][3] += a1 * b.w;
            acc[2][0] += a2 * b.x; acc[2][1] += a2 * b.y; acc[2][2] += a2 * b.z; acc[2][3] += a2 * b.w;
            acc[3][0] += a3 * b.x; acc[3][1] += a3 * b.y; acc[3][2] += a3 * b.z; acc[3][3] += a3 * b.w;
        }
        __syncthreads();
    }

    __nv_bfloat16* oh = (mode == 0) ? g_Qh : (mode == 1) ? g_Kh : g_Vh;
    __nv_bfloat16* ol = (mode == 0) ? g_Ql : (mode == 1) ? g_Kl : g_Vl;
    int col = col0 + tx * 4;
#pragma unroll
    for (int i = 0; i < 4; i++) {
        int gr = row0 + ty * 4 + i;
        float r0, r1, r2, r3;
        if (mode == 2) {
            r0 = acc[i][0]; r1 = acc[i][1]; r2 = acc[i][2]; r3 = acc[i][3];
        } else {
            int s = gr & (S_LEN - 1);
            float4 t0 = g_tab[s * 128 + (col >> 1)];
            float4 t1 = g_tab[s * 128 + (col >> 1) + 1];
            float sc0 = (mode == 0) ? t0.z : t0.w;
            float sc1 = (mode == 0) ? t1.z : t1.w;
            float sn0 = t0.x * sc0, cs0 = t0.y * sc0;
            float sn1 = t1.x * sc1, cs1 = t1.y * sc1;
            r0 = acc[i][0] * cs0 - acc[i][1] * sn0;
            r1 = acc[i][1] * cs0 + acc[i][0] * sn0;
            r2 = acc[i][2] * cs1 - acc[i][3] * sn1;
            r3 = acc[i][3] * cs1 + acc[i][2] * sn1;
        }
        uint2 hw, lw;
        split2(r0, r1, hw.x, lw.x);
        split2(r2, r3, hw.y, lw.y);
        *(uint2*)(oh + (size_t)gr * HID + col) = hw;
        *(uint2*)(ol + (size_t)gr * HID + col) = lw;
    }
}

// ---------------------------------------------------------------------------
// Raw mma.sync (FA2-style) retention attention, windowed (d <= ~640).
// CTA: 128 q-rows, 8 warps x 16 rows, kv tile 32.
// Q hi/lo resident in smem; K/V hi/lo single-buffered with cp.async overlap.
// S and P live in registers (acc layout == a-frag layout).
// ---------------------------------------------------------------------------
#define LQK 264                // bf16 elems per smem row (256 + 8 pad)
#define E_QH 0
#define E_QL 33792
#define E_KH 67584
#define E_KL 76032
#define E_VH 84480
#define E_VL 92928
#define SMEM_BYTES (101376 * 2)   // 202752 B

__device__ __forceinline__ void load_k32(uint32_t sb, int bn, int j0, int t) {
#pragma unroll
    for (int i = 0; i < 8; i++) {
        int idx = t + i * 256;                 // 2048 chunks of 16B
        int plane = idx >> 10, rem = idx & 1023;
        int row = rem >> 5, c = rem & 31;
        uint32_t dst = sb + (uint32_t)((plane ? E_KL : E_KH) + row * LQK + c * 8) * 2;
        const __nv_bfloat16* src = (plane ? g_Kl : g_Kh) +
                                   ((size_t)bn * S_LEN + j0 + row) * HID + c * 8;
        cpa16(dst, src);
    }
}
__device__ __forceinline__ void load_v32(uint32_t sb, int bn, int j0, int t) {
#pragma unroll
    for (int i = 0; i < 8; i++) {
        int idx = t + i * 256;
        int plane = idx >> 10, rem = idx & 1023;
        int row = rem >> 5, c = rem & 31;
        uint32_t dst = sb + (uint32_t)((plane ? E_VL : E_VH) + row * LQK + c * 8) * 2;
        const __nv_bfloat16* src = (plane ? g_Vl : g_Vh) +
                                   ((size_t)bn * S_LEN + j0 + row) * HID + c * 8;
        cpa16(dst, src);
    }
}

__global__ void __launch_bounds__(256, 1) attn_kernel(float* __restrict__ out) {
    extern __shared__ __align__(128) __nv_bfloat16 smattn[];
    uint32_t sb = smem_u32(smattn);
    int t = threadIdx.x, wid = t >> 5, l = t & 31;

    int qt = 15 - (blockIdx.x >> 4);   // heavy q-tiles first
    int bn = blockIdx.x & 15;
    int q0 = qt * 128;
    int jlo = max(0, qt * 4 - 16);     // window: drop d >= 513 (gamma^513 ~ 8e-8)
    int jhi = qt * 4 + 3;

    // ---- prologue loads: Q (hi+lo), K(jlo), V(jlo) ----
#pragma unroll
    for (int i = 0; i < 32; i++) {
        int idx = t + i * 256;                 // 8192 chunks
        int plane = idx >> 12, rem = idx & 4095;
        int row = rem >> 5, c = rem & 31;
        uint32_t dst = sb + (uint32_t)((plane ? E_QL : E_QH) + row * LQK + c * 8) * 2;
        const __nv_bfloat16* src = (plane ? g_Ql : g_Qh) +
                                   ((size_t)bn * S_LEN + q0 + row) * HID + c * 8;
        cpa16(dst, src);
    }
    load_k32(sb, bn, jlo * 32, t);
    load_v32(sb, bn, jlo * 32, t);
    CPA_COMMIT();

    // ---- per-lane ldmatrix offsets ----
    int rowA = (l & 7) + ((l >> 3) & 1) * 8;   // Q (no-trans) / V (trans) pattern
    int colA = (l >> 4) * 8;
    int rowK = (l & 7) + ((l >> 4) & 1) * 8;   // K (no-trans) pattern
    int colK = ((l >> 3) & 1) * 8;

    uint32_t qh_b = sb + (uint32_t)(E_QH + (wid * 16 + rowA) * LQK + colA) * 2;
    uint32_t ql_b = sb + (uint32_t)(E_QL + (wid * 16 + rowA) * LQK + colA) * 2;
    uint32_t kh_b = sb + (uint32_t)(E_KH + rowK * LQK + colK) * 2;
    uint32_t kl_b = sb + (uint32_t)(E_KL + rowK * LQK + colK) * 2;
    uint32_t vh_b = sb + (uint32_t)(E_VH + rowA * LQK + colA) * 2;
    uint32_t vl_b = sb + (uint32_t)(E_VL + rowA * LQK + colA) * 2;

    float o[32][4];
#pragma unroll
    for (int i = 0; i < 32; i++)
#pragma unroll
        for (int j = 0; j < 4; j++) o[i][j] = 0.f;

    CPA_WAIT(0);
    __syncthreads();

    int r0g = q0 + wid * 16 + (l >> 2);

    for (int kt = jlo; kt <= jhi; kt++) {
        int j0 = kt * 32;

        // ---- S = Q K^T (split-3), S in registers ----
        float sa[4][4];
#pragma unroll
        for (int i = 0; i < 4; i++)
#pragma unroll
            for (int j = 0; j < 4; j++) sa[i][j] = 0.f;

#pragma unroll 4
        for (int kc = 0; kc < 16; kc++) {
            uint32_t aH[4], aL[4], bh[8], bl[8];
            ldsm4(aH, qh_b + kc * 32);
            ldsm4(aL, ql_b + kc * 32);
            ldsm4(bh,     kh_b + kc * 32);
            ldsm4(bh + 4, kh_b + 16 * LQK * 2 + kc * 32);
            ldsm4(bl,     kl_b + kc * 32);
            ldsm4(bl + 4, kl_b + 16 * LQK * 2 + kc * 32);
#pragma unroll
            for (int tt = 0; tt < 4; tt++) {
                mma16816(sa[tt], aH, bh + tt * 2);
                mma16816(sa[tt], aH, bl + tt * 2);
                mma16816(sa[tt], aL, bh + tt * 2);
            }
        }
        __syncthreads();                       // K consumed by all warps

        if (kt < jhi) { load_k32(sb, bn, j0 + 32, t); CPA_COMMIT(); }

        // ---- decay + causal mask + bf16 split, all in registers ----
        // c0/c1 at row r0g, c2/c3 at row r0g+8 (decay x gamma^8, mask d+8)
        uint32_t pH[2][4], pL[2][4];
#pragma unroll
        for (int tt = 0; tt < 4; tt++) {
            int c0 = j0 + tt * 8 + 2 * (l & 3);
            int d = r0g - c0;
            float e0 = exp2f((float)d * L2G);
            float e8 = e0 * G8C;
            float p0 = (d >= 0)  ? sa[tt][0] * e0 : 0.f;
            float p1 = (d >= 1)  ? sa[tt][1] * (e0 * IGAM) : 0.f;
            float p2 = (d >= -8) ? sa[tt][2] * e8 : 0.f;
            float p3 = (d >= -7) ? sa[tt][3] * (e8 * IGAM) : 0.f;
            uint32_t h01, l01, h23, l23;
            split2(p0, p1, h01, l01);
            split2(p2, p3, h23, l23);
            int c2 = tt >> 1, jj = tt & 1;
            pH[c2][2 * jj + 0] = h01;  pH[c2][2 * jj + 1] = h23;
            pL[c2][2 * jj + 0] = l01;  pL[c2][2 * jj + 1] = l23;
        }

        if (kt < jhi) { CPA_WAIT(1); } else { CPA_WAIT(0); }
        __syncthreads();                       // V(kt) visible to all

        // ---- O += P V (split-3) ----
#pragma unroll
        for (int c2 = 0; c2 < 2; c2++) {
#pragma unroll
            for (int nb = 0; nb < 16; nb++) {
                uint32_t bh[4], bl[4];
                ldsm4t(bh, vh_b + c2 * 16 * LQK * 2 + nb * 32);
                ldsm4t(bl, vl_b + c2 * 16 * LQK * 2 + nb * 32);
                mma16816(o[2 * nb],     pH[c2], bh);
                mma16816(o[2 * nb],     pH[c2], bl);
                mma16816(o[2 * nb],     pL[c2], bh);
                mma16816(o[2 * nb + 1], pH[c2], bh + 2);
                mma16816(o[2 * nb + 1], pH[c2], bl + 2);
                mma16816(o[2 * nb + 1], pL[c2], bh + 2);
            }
        }
        __syncthreads();                       // V consumed

        if (kt < jhi) {
            load_v32(sb, bn, j0 + 32, t);      // V(kt+1)  [R6 bug was +64]
            CPA_COMMIT();
            CPA_WAIT(1);                       // K(kt+1) done
        }
        __syncthreads();
    }

    // ---- store O ----
    float* ob = out + ((size_t)bn * S_LEN + r0g) * HID + 2 * (l & 3);
#pragma unroll
    for (int tt = 0; tt < 32; tt++) {
        *(float2*)(ob + tt * 8)           = make_float2(o[tt][0], o[tt][1]);
        *(float2*)(ob + 8 * HID + tt * 8) = make_float2(o[tt][2], o[tt][3]);
    }
}

// ---------------------------------------------------------------------------
extern "C" void kernel_launch(void* const* d_in, const int* in_sizes, int n_in,
                              void* d_out, int out_size) {
    const float* X  = (const float*)d_in[0];
    const float* Wq = (const float*)d_in[1];
    const float* Wk = (const float*)d_in[2];
    const float* Wv = (const float*)d_in[3];
    float* out = (float*)d_out;

    tab_kernel<<<(S_LEN * 128 + 255) / 256, 256>>>();

    dim3 pgrid(HID / 64, M_ROWS / 64, 3);
    proj_kernel<<<pgrid, dim3(16, 16)>>>(X, Wq, Wk, Wv);

    cudaFuncSetAttribute(attn_kernel, cudaFuncAttributeMaxDynamicSharedMemorySize, SMEM_BYTES);
    attn_kernel<<<16 * BN, 256, SMEM_BYTES>>>(out);
}

// round 8
// speedup vs baseline: 5.3596x; 1.3937x over previous
#include <cuda_runtime.h>
#include <cuda_bf16.h>
#include <math.h>
#include <stdint.h>

#define S_LEN 2048
#define HID   256
#define BN    16
#define M_ROWS (BN * S_LEN)   // 32768

#define L2G  (-0.04580369f)              // log2(0.96875)
#define IGAM (1.03225806451612903f)      // 1/0.96875
#define G8C  (0.775700596198439598f)     // 0.96875^8 (exact)

// ---------------------------------------------------------------------------
// Device-global scratch (bf16 hi/lo splits)
// ---------------------------------------------------------------------------
__device__ __align__(256) __nv_bfloat16 g_Xh[(size_t)M_ROWS * HID];
__device__ __align__(256) __nv_bfloat16 g_Xl[(size_t)M_ROWS * HID];
__device__ __align__(256) __nv_bfloat16 g_Wh[3 * HID * HID];
__device__ __align__(256) __nv_bfloat16 g_Wl[3 * HID * HID];
__device__ __align__(256) __nv_bfloat16 g_Qh[(size_t)M_ROWS * HID];
__device__ __align__(256) __nv_bfloat16 g_Ql[(size_t)M_ROWS * HID];
__device__ __align__(256) __nv_bfloat16 g_Kh[(size_t)M_ROWS * HID];
__device__ __align__(256) __nv_bfloat16 g_Kl[(size_t)M_ROWS * HID];
__device__ __align__(256) __nv_bfloat16 g_Vh[(size_t)M_ROWS * HID];
__device__ __align__(256) __nv_bfloat16 g_Vl[(size_t)M_ROWS * HID];
__device__ float4 g_tab[S_LEN * 128];   // {sin, cos, scale, 1/scale}

// ---------------------------------------------------------------------------
// helpers
// ---------------------------------------------------------------------------
__device__ __forceinline__ uint32_t smem_u32(const void* p) {
    uint32_t a;
    asm("{ .reg .u64 t; cvta.to.shared.u64 t, %1; cvt.u32.u64 %0, t; }" : "=r"(a) : "l"(p));
    return a;
}
__device__ __forceinline__ void cpa16(uint32_t dst, const void* src) {
    asm volatile("cp.async.cg.shared.global [%0], [%1], 16;" :: "r"(dst), "l"(src));
}
#define CPA_COMMIT() asm volatile("cp.async.commit_group;" ::: "memory")
#define CPA_WAIT(n)  asm volatile("cp.async.wait_group %0;" :: "n"(n) : "memory")

__device__ __forceinline__ void ldsm4(uint32_t* r, uint32_t a) {
    asm volatile("ldmatrix.sync.aligned.m8n8.x4.shared.b16 {%0,%1,%2,%3}, [%4];"
                 : "=r"(r[0]), "=r"(r[1]), "=r"(r[2]), "=r"(r[3]) : "r"(a));
}
__device__ __forceinline__ void ldsm4t(uint32_t* r, uint32_t a) {
    asm volatile("ldmatrix.sync.aligned.m8n8.x4.trans.shared.b16 {%0,%1,%2,%3}, [%4];"
                 : "=r"(r[0]), "=r"(r[1]), "=r"(r[2]), "=r"(r[3]) : "r"(a));
}
__device__ __forceinline__ void mma16816(float* c, const uint32_t* a, const uint32_t* b) {
    asm volatile("mma.sync.aligned.m16n8k16.row.col.f32.bf16.bf16.f32 "
                 "{%0,%1,%2,%3}, {%4,%5,%6,%7}, {%8,%9}, {%0,%1,%2,%3};"
                 : "+f"(c[0]), "+f"(c[1]), "+f"(c[2]), "+f"(c[3])
                 : "r"(a[0]), "r"(a[1]), "r"(a[2]), "r"(a[3]), "r"(b[0]), "r"(b[1]));
}
__device__ __forceinline__ void split2(float a, float b, uint32_t& h, uint32_t& l) {
    __nv_bfloat162 hh = __floats2bfloat162_rn(a, b);
    __nv_bfloat162 ll = __floats2bfloat162_rn(a - __bfloat162float(hh.x),
                                              b - __bfloat162float(hh.y));
    h = *(uint32_t*)&hh;
    l = *(uint32_t*)&ll;
}

// ---------------------------------------------------------------------------
// xpos table
// ---------------------------------------------------------------------------
__global__ void tab_kernel() {
    int idx = blockIdx.x * 256 + threadIdx.x;
    if (idx >= S_LEN * 128) return;
    int s = idx >> 7, i = idx & 127;
    float inv_freq = (float)exp2(-(double)i * (13.287712379549449 / 128.0));
    float sn, cs;
    sincosf((float)s * inv_freq, &sn, &cs);
    float base  = ((float)(2 * i) + 102.4f) / 358.4f;
    float scale = exp2f(log2f(base) * ((float)s * (1.0f / 512.0f)));
    g_tab[idx] = make_float4(sn, cs, scale, 1.0f / scale);
}

// ---------------------------------------------------------------------------
// X split: fp32 -> bf16 hi/lo
// ---------------------------------------------------------------------------
__global__ void xsplit_kernel(const float* __restrict__ X) {
    size_t i = ((size_t)blockIdx.x * 256 + threadIdx.x) * 4;
    float4 v = *(const float4*)(X + i);
    uint2 hw, lw;
    split2(v.x, v.y, hw.x, lw.x);
    split2(v.z, v.w, hw.y, lw.y);
    *(uint2*)(g_Xh + i) = hw;
    *(uint2*)(g_Xl + i) = lw;
}

// W split: 3 x 256 x 256
__global__ void wsplit_kernel(const float* __restrict__ Wq,
                              const float* __restrict__ Wk,
                              const float* __restrict__ Wv) {
    int idx = blockIdx.x * 256 + threadIdx.x;    // over 3*65536/2
    int mode = idx >> 15, pos = (idx & 32767) * 2;
    const float* W = (mode == 0) ? Wq : (mode == 1) ? Wk : Wv;
    float a = W[pos], b = W[pos + 1];
    uint32_t h, l;
    split2(a, b, h, l);
    *(uint32_t*)(g_Wh + mode * 65536 + pos) = h;
    *(uint32_t*)(g_Wl + mode * 65536 + pos) = l;
}

// ---------------------------------------------------------------------------
// Tensor-core QKV projection (split-3 bf16 mma.sync) + fused xpos epilogue.
// grid: (M_ROWS/128, 3). CTA: 128 rows x 256 cols, K=256 in 4 chunks of 64,
// double-buffered cp.async. 8 warps x 16 rows.
// ---------------------------------------------------------------------------
#define LX 72      // X smem row stride (64+8) bf16
#define LW 264     // W smem row stride (256+8) bf16
#define PCHUNK 52224   // elems per buffer: 2*128*72 + 2*64*264
#define P_XH 0
#define P_XL 9216
#define P_WH 18432
#define P_WL 35328
#define PROJ_SMEM (PCHUNK * 2 * 2)   // 208896 B

__device__ __forceinline__ void proj_load(uint32_t sb, int buf, int row0, int mode,
                                          int k0, int t) {
    uint32_t b0 = (uint32_t)(buf * PCHUNK);
    // X: 2 planes x 128 rows x 8 16B-units
#pragma unroll
    for (int i = 0; i < 8; i++) {
        int idx = t + i * 256;
        int plane = idx >> 10, rem = idx & 1023;
        int row = rem >> 3, c = rem & 7;
        uint32_t dst = sb + (b0 + (plane ? P_XL : P_XH) + row * LX + c * 8) * 2;
        const __nv_bfloat16* src = (plane ? g_Xl : g_Xh) +
                                   ((size_t)(row0 + row)) * HID + k0 + c * 8;
        cpa16(dst, src);
    }
    // W: 2 planes x 64 rows x 32 16B-units
#pragma unroll
    for (int i = 0; i < 16; i++) {
        int idx = t + i * 256;
        int plane = idx >> 11, rem = idx & 2047;
        int row = rem >> 5, c = rem & 31;
        uint32_t dst = sb + (b0 + (plane ? P_WL : P_WH) + row * LW + c * 8) * 2;
        const __nv_bfloat16* src = (plane ? g_Wl : g_Wh) +
                                   mode * 65536 + (k0 + row) * HID + c * 8;
        cpa16(dst, src);
    }
}

__global__ void __launch_bounds__(256, 1) proj_kernel() {
    extern __shared__ __align__(128) __nv_bfloat16 smproj[];
    uint32_t sb = smem_u32(smproj);
    int t = threadIdx.x, wid = t >> 5, l = t & 31;
    int row0 = blockIdx.x * 128;
    int mode = blockIdx.y;

    int rowA = (l & 7) + ((l >> 3) & 1) * 8;
    int colA = (l >> 4) * 8;

    float o[32][4];
#pragma unroll
    for (int i = 0; i < 32; i++)
#pragma unroll
        for (int j = 0; j < 4; j++) o[i][j] = 0.f;

    proj_load(sb, 0, row0, mode, 0, t);
    CPA_COMMIT();

    for (int ch = 0; ch < 4; ch++) {
        int buf = ch & 1;
        if (ch < 3) { proj_load(sb, 1 - buf, row0, mode, (ch + 1) * 64, t); CPA_COMMIT(); CPA_WAIT(1); }
        else        { CPA_WAIT(0); }
        __syncthreads();

        uint32_t b0 = (uint32_t)(buf * PCHUNK);
        uint32_t xh_b = sb + (b0 + P_XH + (wid * 16 + rowA) * LX + colA) * 2;
        uint32_t xl_b = sb + (b0 + P_XL + (wid * 16 + rowA) * LX + colA) * 2;
        uint32_t wh_b = sb + (b0 + P_WH + rowA * LW + colA) * 2;
        uint32_t wl_b = sb + (b0 + P_WL + rowA * LW + colA) * 2;

#pragma unroll
        for (int ks = 0; ks < 4; ks++) {
            uint32_t aH[4], aL[4];
            ldsm4(aH, xh_b + ks * 32);
            ldsm4(aL, xl_b + ks * 32);
#pragma unroll
            for (int n16 = 0; n16 < 16; n16++) {
                uint32_t bh[4], bl[4];
                ldsm4t(bh, wh_b + ks * 16 * LW * 2 + n16 * 32);
                ldsm4t(bl, wl_b + ks * 16 * LW * 2 + n16 * 32);
                mma16816(o[2 * n16],     aH, bh);
                mma16816(o[2 * n16],     aH, bl);
                mma16816(o[2 * n16],     aL, bh);
                mma16816(o[2 * n16 + 1], aH, bh + 2);
                mma16816(o[2 * n16 + 1], aH, bl + 2);
                mma16816(o[2 * n16 + 1], aL, bh + 2);
            }
        }
        __syncthreads();
    }

    // ---- epilogue: optional xpos rotation, split, store ----
    __nv_bfloat16* oh = (mode == 0) ? g_Qh : (mode == 1) ? g_Kh : g_Vh;
    __nv_bfloat16* ol = (mode == 0) ? g_Ql : (mode == 1) ? g_Kl : g_Vl;
    int r1 = row0 + wid * 16 + (l >> 2);
    int r2 = r1 + 8;
    int s1 = r1 & (S_LEN - 1), s2 = r2 & (S_LEN - 1);

#pragma unroll
    for (int nb = 0; nb < 32; nb++) {
        int col = nb * 8 + 2 * (l & 3);
        float a0 = o[nb][0], a1 = o[nb][1];   // row r1, cols col, col+1
        float b0 = o[nb][2], b1 = o[nb][3];   // row r2
        if (mode != 2) {
            float4 t1 = g_tab[s1 * 128 + (col >> 1)];
            float4 t2 = g_tab[s2 * 128 + (col >> 1)];
            float sc1 = (mode == 0) ? t1.z : t1.w;
            float sc2 = (mode == 0) ? t2.z : t2.w;
            float sn1 = t1.x * sc1, cs1 = t1.y * sc1;
            float sn2 = t2.x * sc2, cs2 = t2.y * sc2;
            float n0 = a0 * cs1 - a1 * sn1;
            float n1 = a1 * cs1 + a0 * sn1;
            float m0 = b0 * cs2 - b1 * sn2;
            float m1 = b1 * cs2 + b0 * sn2;
            a0 = n0; a1 = n1; b0 = m0; b1 = m1;
        }
        uint32_t h1, l1, h2, l2;
        split2(a0, a1, h1, l1);
        split2(b0, b1, h2, l2);
        *(uint32_t*)(oh + (size_t)r1 * HID + col) = h1;
        *(uint32_t*)(ol + (size_t)r1 * HID + col) = l1;
        *(uint32_t*)(oh + (size_t)r2 * HID + col) = h2;
        *(uint32_t*)(ol + (size_t)r2 * HID + col) = l2;
    }
}

// ---------------------------------------------------------------------------
// Raw mma.sync (FA2-style) retention attention, windowed (d <= ~640).
// ---------------------------------------------------------------------------
#define LQK 264                // bf16 elems per smem row (256 + 8 pad)
#define E_QH 0
#define E_QL 33792
#define E_KH 67584
#define E_KL 76032
#define E_VH 84480
#define E_VL 92928
#define SMEM_BYTES (101376 * 2)   // 202752 B

__device__ __forceinline__ void load_k32(uint32_t sb, int bn, int j0, int t) {
#pragma unroll
    for (int i = 0; i < 8; i++) {
        int idx = t + i * 256;
        int plane = idx >> 10, rem = idx & 1023;
        int row = rem >> 5, c = rem & 31;
        uint32_t dst = sb + (uint32_t)((plane ? E_KL : E_KH) + row * LQK + c * 8) * 2;
        const __nv_bfloat16* src = (plane ? g_Kl : g_Kh) +
                                   ((size_t)bn * S_LEN + j0 + row) * HID + c * 8;
        cpa16(dst, src);
    }
}
__device__ __forceinline__ void load_v32(uint32_t sb, int bn, int j0, int t) {
#pragma unroll
    for (int i = 0; i < 8; i++) {
        int idx = t + i * 256;
        int plane = idx >> 10, rem = idx & 1023;
        int row = rem >> 5, c = rem & 31;
        uint32_t dst = sb + (uint32_t)((plane ? E_VL : E_VH) + row * LQK + c * 8) * 2;
        const __nv_bfloat16* src = (plane ? g_Vl : g_Vh) +
                                   ((size_t)bn * S_LEN + j0 + row) * HID + c * 8;
        cpa16(dst, src);
    }
}

__global__ void __launch_bounds__(256, 1) attn_kernel(float* __restrict__ out) {
    extern __shared__ __align__(128) __nv_bfloat16 smattn[];
    uint32_t sb = smem_u32(smattn);
    int t = threadIdx.x, wid = t >> 5, l = t & 31;

    int qt = 15 - (blockIdx.x >> 4);   // heavy q-tiles first
    int bn = blockIdx.x & 15;
    int q0 = qt * 128;
    int jlo = max(0, qt * 4 - 16);     // window: drop d >= 513 (gamma^513 ~ 8e-8)
    int jhi = qt * 4 + 3;

#pragma unroll
    for (int i = 0; i < 32; i++) {
        int idx = t + i * 256;
        int plane = idx >> 12, rem = idx & 4095;
        int row = rem >> 5, c = rem & 31;
        uint32_t dst = sb + (uint32_t)((plane ? E_QL : E_QH) + row * LQK + c * 8) * 2;
        const __nv_bfloat16* src = (plane ? g_Ql : g_Qh) +
                                   ((size_t)bn * S_LEN + q0 + row) * HID + c * 8;
        cpa16(dst, src);
    }
    load_k32(sb, bn, jlo * 32, t);
    load_v32(sb, bn, jlo * 32, t);
    CPA_COMMIT();

    int rowA = (l & 7) + ((l >> 3) & 1) * 8;
    int colA = (l >> 4) * 8;
    int rowK = (l & 7) + ((l >> 4) & 1) * 8;
    int colK = ((l >> 3) & 1) * 8;

    uint32_t qh_b = sb + (uint32_t)(E_QH + (wid * 16 + rowA) * LQK + colA) * 2;
    uint32_t ql_b = sb + (uint32_t)(E_QL + (wid * 16 + rowA) * LQK + colA) * 2;
    uint32_t kh_b = sb + (uint32_t)(E_KH + rowK * LQK + colK) * 2;
    uint32_t kl_b = sb + (uint32_t)(E_KL + rowK * LQK + colK) * 2;
    uint32_t vh_b = sb + (uint32_t)(E_VH + rowA * LQK + colA) * 2;
    uint32_t vl_b = sb + (uint32_t)(E_VL + rowA * LQK + colA) * 2;

    float o[32][4];
#pragma unroll
    for (int i = 0; i < 32; i++)
#pragma unroll
        for (int j = 0; j < 4; j++) o[i][j] = 0.f;

    CPA_WAIT(0);
    __syncthreads();

    int r0g = q0 + wid * 16 + (l >> 2);

    for (int kt = jlo; kt <= jhi; kt++) {
        int j0 = kt * 32;

        float sa[4][4];
#pragma unroll
        for (int i = 0; i < 4; i++)
#pragma unroll
            for (int j = 0; j < 4; j++) sa[i][j] = 0.f;

#pragma unroll 4
        for (int kc = 0; kc < 16; kc++) {
            uint32_t aH[4], aL[4], bh[8], bl[8];
            ldsm4(aH, qh_b + kc * 32);
            ldsm4(aL, ql_b + kc * 32);
            ldsm4(bh,     kh_b + kc * 32);
            ldsm4(bh + 4, kh_b + 16 * LQK * 2 + kc * 32);
            ldsm4(bl,     kl_b + kc * 32);
            ldsm4(bl + 4, kl_b + 16 * LQK * 2 + kc * 32);
#pragma unroll
            for (int tt = 0; tt < 4; tt++) {
                mma16816(sa[tt], aH, bh + tt * 2);
                mma16816(sa[tt], aH, bl + tt * 2);
                mma16816(sa[tt], aL, bh + tt * 2);
            }
        }
        __syncthreads();

        if (kt < jhi) { load_k32(sb, bn, j0 + 32, t); CPA_COMMIT(); }

        uint32_t pH[2][4], pL[2][4];
#pragma unroll
        for (int tt = 0; tt < 4; tt++) {
            int c0 = j0 + tt * 8 + 2 * (l & 3);
            int d = r0g - c0;
            float e0 = exp2f((float)d * L2G);
            float e8 = e0 * G8C;
            float p0 = (d >= 0)  ? sa[tt][0] * e0 : 0.f;
            float p1 = (d >= 1)  ? sa[tt][1] * (e0 * IGAM) : 0.f;
            float p2 = (d >= -8) ? sa[tt][2] * e8 : 0.f;
            float p3 = (d >= -7) ? sa[tt][3] * (e8 * IGAM) : 0.f;
            uint32_t h01, l01, h23, l23;
            split2(p0, p1, h01, l01);
            split2(p2, p3, h23, l23);
            int c2 = tt >> 1, jj = tt & 1;
            pH[c2][2 * jj + 0] = h01;  pH[c2][2 * jj + 1] = h23;
            pL[c2][2 * jj + 0] = l01;  pL[c2][2 * jj + 1] = l23;
        }

        if (kt < jhi) { CPA_WAIT(1); } else { CPA_WAIT(0); }
        __syncthreads();

#pragma unroll
        for (int c2 = 0; c2 < 2; c2++) {
#pragma unroll
            for (int nb = 0; nb < 16; nb++) {
                uint32_t bh[4], bl[4];
                ldsm4t(bh, vh_b + c2 * 16 * LQK * 2 + nb * 32);
                ldsm4t(bl, vl_b + c2 * 16 * LQK * 2 + nb * 32);
                mma16816(o[2 * nb],     pH[c2], bh);
                mma16816(o[2 * nb],     pH[c2], bl);
                mma16816(o[2 * nb],     pL[c2], bh);
                mma16816(o[2 * nb + 1], pH[c2], bh + 2);
                mma16816(o[2 * nb + 1], pH[c2], bl + 2);
                mma16816(o[2 * nb + 1], pL[c2], bh + 2);
            }
        }
        __syncthreads();

        if (kt < jhi) {
            load_v32(sb, bn, j0 + 32, t);      // V(kt+1)
            CPA_COMMIT();
            CPA_WAIT(1);                       // K(kt+1) done
        }
        __syncthreads();
    }

    float* ob = out + ((size_t)bn * S_LEN + r0g) * HID + 2 * (l & 3);
#pragma unroll
    for (int tt = 0; tt < 32; tt++) {
        *(float2*)(ob + tt * 8)           = make_float2(o[tt][0], o[tt][1]);
        *(float2*)(ob + 8 * HID + tt * 8) = make_float2(o[tt][2], o[tt][3]);
    }
}

// ---------------------------------------------------------------------------
extern "C" void kernel_launch(void* const* d_in, const int* in_sizes, int n_in,
                              void* d_out, int out_size) {
    const float* X  = (const float*)d_in[0];
    const float* Wq = (const float*)d_in[1];
    const float* Wk = (const float*)d_in[2];
    const float* Wv = (const float*)d_in[3];
    float* out = (float*)d_out;

    tab_kernel<<<(S_LEN * 128 + 255) / 256, 256>>>();
    xsplit_kernel<<<(M_ROWS * HID / 4) / 256, 256>>>(X);
    wsplit_kernel<<<3 * HID * HID / 2 / 256, 256>>>(Wq, Wk, Wv);

    cudaFuncSetAttribute(proj_kernel, cudaFuncAttributeMaxDynamicSharedMemorySize, PROJ_SMEM);
    proj_kernel<<<dim3(M_ROWS / 128, 3), 256, PROJ_SMEM>>>();

    cudaFuncSetAttribute(attn_kernel, cudaFuncAttributeMaxDynamicSharedMemorySize, SMEM_BYTES);
    attn_kernel<<<16 * BN, 256, SMEM_BYTES>>>(out);
}

// round 9
// speedup vs baseline: 6.2613x; 1.1682x over previous
#include <cuda_runtime.h>
#include <cuda_bf16.h>
#include <math.h>
#include <stdint.h>

#define S_LEN 2048
#define HID   256
#define BN    16
#define M_ROWS (BN * S_LEN)   // 32768

#define L2G  (-0.04580369f)              // log2(0.96875)
#define IGAM (1.03225806451612903f)      // 1/0.96875
#define G8C  (0.775700596198439598f)     // 0.96875^8 (exact)

// ---------------------------------------------------------------------------
// Device-global scratch (bf16 hi/lo splits)
// ---------------------------------------------------------------------------
__device__ __align__(256) __nv_bfloat16 g_Xh[(size_t)M_ROWS * HID];
__device__ __align__(256) __nv_bfloat16 g_Xl[(size_t)M_ROWS * HID];
__device__ __align__(256) __nv_bfloat16 g_Wh[3 * HID * HID];
__device__ __align__(256) __nv_bfloat16 g_Wl[3 * HID * HID];
__device__ __align__(256) __nv_bfloat16 g_Qh[(size_t)M_ROWS * HID];
__device__ __align__(256) __nv_bfloat16 g_Ql[(size_t)M_ROWS * HID];
__device__ __align__(256) __nv_bfloat16 g_Kh[(size_t)M_ROWS * HID];
__device__ __align__(256) __nv_bfloat16 g_Kl[(size_t)M_ROWS * HID];
__device__ __align__(256) __nv_bfloat16 g_Vh[(size_t)M_ROWS * HID];
__device__ __align__(256) __nv_bfloat16 g_Vl[(size_t)M_ROWS * HID];
__device__ float4 g_tab[S_LEN * 128];   // {sin, cos, scale, 1/scale}

// ---------------------------------------------------------------------------
// helpers
// ---------------------------------------------------------------------------
__device__ __forceinline__ uint32_t smem_u32(const void* p) {
    uint32_t a;
    asm("{ .reg .u64 t; cvta.to.shared.u64 t, %1; cvt.u32.u64 %0, t; }" : "=r"(a) : "l"(p));
    return a;
}
__device__ __forceinline__ void cpa16(uint32_t dst, const void* src) {
    asm volatile("cp.async.cg.shared.global [%0], [%1], 16;" :: "r"(dst), "l"(src));
}
#define CPA_COMMIT() asm volatile("cp.async.commit_group;" ::: "memory")
#define CPA_WAIT(n)  asm volatile("cp.async.wait_group %0;" :: "n"(n) : "memory")

__device__ __forceinline__ void ldsm4(uint32_t* r, uint32_t a) {
    asm volatile("ldmatrix.sync.aligned.m8n8.x4.shared.b16 {%0,%1,%2,%3}, [%4];"
                 : "=r"(r[0]), "=r"(r[1]), "=r"(r[2]), "=r"(r[3]) : "r"(a));
}
__device__ __forceinline__ void ldsm4t(uint32_t* r, uint32_t a) {
    asm volatile("ldmatrix.sync.aligned.m8n8.x4.trans.shared.b16 {%0,%1,%2,%3}, [%4];"
                 : "=r"(r[0]), "=r"(r[1]), "=r"(r[2]), "=r"(r[3]) : "r"(a));
}
__device__ __forceinline__ void mma16816(float* c, const uint32_t* a, const uint32_t* b) {
    asm volatile("mma.sync.aligned.m16n8k16.row.col.f32.bf16.bf16.f32 "
                 "{%0,%1,%2,%3}, {%4,%5,%6,%7}, {%8,%9}, {%0,%1,%2,%3};"
                 : "+f"(c[0]), "+f"(c[1]), "+f"(c[2]), "+f"(c[3])
                 : "r"(a[0]), "r"(a[1]), "r"(a[2]), "r"(a[3]), "r"(b[0]), "r"(b[1]));
}
__device__ __forceinline__ void split2(float a, float b, uint32_t& h, uint32_t& l) {
    __nv_bfloat162 hh = __floats2bfloat162_rn(a, b);
    __nv_bfloat162 ll = __floats2bfloat162_rn(a - __bfloat162float(hh.x),
                                              b - __bfloat162float(hh.y));
    h = *(uint32_t*)&hh;
    l = *(uint32_t*)&ll;
}

// ---------------------------------------------------------------------------
// xpos table
// ---------------------------------------------------------------------------
__global__ void tab_kernel() {
    int idx = blockIdx.x * 256 + threadIdx.x;
    if (idx >= S_LEN * 128) return;
    int s = idx >> 7, i = idx & 127;
    float inv_freq = (float)exp2(-(double)i * (13.287712379549449 / 128.0));
    float sn, cs;
    sincosf((float)s * inv_freq, &sn, &cs);
    float base  = ((float)(2 * i) + 102.4f) / 358.4f;
    float scale = exp2f(log2f(base) * ((float)s * (1.0f / 512.0f)));
    g_tab[idx] = make_float4(sn, cs, scale, 1.0f / scale);
}

// ---------------------------------------------------------------------------
// X split: fp32 -> bf16 hi/lo
// ---------------------------------------------------------------------------
__global__ void xsplit_kernel(const float* __restrict__ X) {
    size_t i = ((size_t)blockIdx.x * 256 + threadIdx.x) * 4;
    float4 v = *(const float4*)(X + i);
    uint2 hw, lw;
    split2(v.x, v.y, hw.x, lw.x);
    split2(v.z, v.w, hw.y, lw.y);
    *(uint2*)(g_Xh + i) = hw;
    *(uint2*)(g_Xl + i) = lw;
}

// W split: 3 x 256 x 256
__global__ void wsplit_kernel(const float* __restrict__ Wq,
                              const float* __restrict__ Wk,
                              const float* __restrict__ Wv) {
    int idx = blockIdx.x * 256 + threadIdx.x;
    int mode = idx >> 15, pos = (idx & 32767) * 2;
    const float* W = (mode == 0) ? Wq : (mode == 1) ? Wk : Wv;
    float a = W[pos], b = W[pos + 1];
    uint32_t h, l;
    split2(a, b, h, l);
    *(uint32_t*)(g_Wh + mode * 65536 + pos) = h;
    *(uint32_t*)(g_Wl + mode * 65536 + pos) = l;
}

// ---------------------------------------------------------------------------
// Tensor-core QKV projection (split-3 bf16 mma.sync) + fused xpos epilogue.
// grid: (M_ROWS/128, 3). CTA: 512 threads = 16 warps; row-group = wid>>1
// (16 rows), N-half = wid&1 (128 cols). 64 accum regs/thread -> no spills.
// K=256 in 4 chunks of 64, double-buffered cp.async.
// ---------------------------------------------------------------------------
#define LX 72      // X smem row stride (64+8) bf16
#define LW 264     // W smem row stride (256+8) bf16
#define PCHUNK 52224   // elems per buffer: 2*128*72 + 2*64*264
#define P_XH 0
#define P_XL 9216
#define P_WH 18432
#define P_WL 35328
#define PROJ_SMEM (PCHUNK * 2 * 2)   // 208896 B

__device__ __forceinline__ void proj_load(uint32_t sb, int buf, int row0, int mode,
                                          int k0, int t) {
    uint32_t b0 = (uint32_t)(buf * PCHUNK);
    // X: 2 planes x 128 rows x 8 16B-units = 2048 units
#pragma unroll
    for (int i = 0; i < 4; i++) {
        int idx = t + i * 512;
        int plane = idx >> 10, rem = idx & 1023;
        int row = rem >> 3, c = rem & 7;
        uint32_t dst = sb + (b0 + (plane ? P_XL : P_XH) + row * LX + c * 8) * 2;
        const __nv_bfloat16* src = (plane ? g_Xl : g_Xh) +
                                   ((size_t)(row0 + row)) * HID + k0 + c * 8;
        cpa16(dst, src);
    }
    // W: 2 planes x 64 rows x 32 16B-units = 4096 units
#pragma unroll
    for (int i = 0; i < 8; i++) {
        int idx = t + i * 512;
        int plane = idx >> 11, rem = idx & 2047;
        int row = rem >> 5, c = rem & 31;
        uint32_t dst = sb + (b0 + (plane ? P_WL : P_WH) + row * LW + c * 8) * 2;
        const __nv_bfloat16* src = (plane ? g_Wl : g_Wh) +
                                   mode * 65536 + (k0 + row) * HID + c * 8;
        cpa16(dst, src);
    }
}

__global__ void __launch_bounds__(512, 1) proj_kernel() {
    extern __shared__ __align__(128) __nv_bfloat16 smproj[];
    uint32_t sb = smem_u32(smproj);
    int t = threadIdx.x, wid = t >> 5, l = t & 31;
    int g  = wid >> 1;        // row group 0..7 (16 rows)
    int nh = wid & 1;         // n half 0..1 (128 cols)
    int row0 = blockIdx.x * 128;
    int mode = blockIdx.y;

    int rowA = (l & 7) + ((l >> 3) & 1) * 8;
    int colA = (l >> 4) * 8;

    float o[16][4];
#pragma unroll
    for (int i = 0; i < 16; i++)
#pragma unroll
        for (int j = 0; j < 4; j++) o[i][j] = 0.f;

    proj_load(sb, 0, row0, mode, 0, t);
    CPA_COMMIT();

    for (int ch = 0; ch < 4; ch++) {
        int buf = ch & 1;
        if (ch < 3) { proj_load(sb, 1 - buf, row0, mode, (ch + 1) * 64, t); CPA_COMMIT(); CPA_WAIT(1); }
        else        { CPA_WAIT(0); }
        __syncthreads();

        uint32_t b0 = (uint32_t)(buf * PCHUNK);
        uint32_t xh_b = sb + (b0 + P_XH + (g * 16 + rowA) * LX + colA) * 2;
        uint32_t xl_b = sb + (b0 + P_XL + (g * 16 + rowA) * LX + colA) * 2;
        uint32_t wh_b = sb + (b0 + P_WH + rowA * LW + nh * 128 + colA) * 2;
        uint32_t wl_b = sb + (b0 + P_WL + rowA * LW + nh * 128 + colA) * 2;

#pragma unroll
        for (int ks = 0; ks < 4; ks++) {
            uint32_t aH[4], aL[4];
            ldsm4(aH, xh_b + ks * 32);
            ldsm4(aL, xl_b + ks * 32);
#pragma unroll
            for (int nb = 0; nb < 8; nb++) {
                uint32_t bh[4], bl[4];
                ldsm4t(bh, wh_b + ks * 16 * LW * 2 + nb * 32);
                ldsm4t(bl, wl_b + ks * 16 * LW * 2 + nb * 32);
                mma16816(o[2 * nb],     aH, bh);
                mma16816(o[2 * nb],     aH, bl);
                mma16816(o[2 * nb],     aL, bh);
                mma16816(o[2 * nb + 1], aH, bh + 2);
                mma16816(o[2 * nb + 1], aH, bl + 2);
                mma16816(o[2 * nb + 1], aL, bh + 2);
            }
        }
        __syncthreads();
    }

    // ---- epilogue: optional xpos rotation, split, store ----
    __nv_bfloat16* oh = (mode == 0) ? g_Qh : (mode == 1) ? g_Kh : g_Vh;
    __nv_bfloat16* ol = (mode == 0) ? g_Ql : (mode == 1) ? g_Kl : g_Vl;
    int r1 = row0 + g * 16 + (l >> 2);
    int r2 = r1 + 8;
    int s1 = r1 & (S_LEN - 1), s2 = r2 & (S_LEN - 1);

#pragma unroll
    for (int nb = 0; nb < 16; nb++) {
        int col = nh * 128 + nb * 8 + 2 * (l & 3);
        float a0 = o[nb][0], a1 = o[nb][1];
        float b0 = o[nb][2], b1 = o[nb][3];
        if (mode != 2) {
            float4 t1 = g_tab[s1 * 128 + (col >> 1)];
            float4 t2 = g_tab[s2 * 128 + (col >> 1)];
            float sc1 = (mode == 0) ? t1.z : t1.w;
            float sc2 = (mode == 0) ? t2.z : t2.w;
            float sn1 = t1.x * sc1, cs1 = t1.y * sc1;
            float sn2 = t2.x * sc2, cs2 = t2.y * sc2;
            float n0 = a0 * cs1 - a1 * sn1;
            float n1 = a1 * cs1 + a0 * sn1;
            float m0 = b0 * cs2 - b1 * sn2;
            float m1 = b1 * cs2 + b0 * sn2;
            a0 = n0; a1 = n1; b0 = m0; b1 = m1;
        }
        uint32_t h1, l1, h2, l2;
        split2(a0, a1, h1, l1);
        split2(b0, b1, h2, l2);
        *(uint32_t*)(oh + (size_t)r1 * HID + col) = h1;
        *(uint32_t*)(ol + (size_t)r1 * HID + col) = l1;
        *(uint32_t*)(oh + (size_t)r2 * HID + col) = h2;
        *(uint32_t*)(ol + (size_t)r2 * HID + col) = l2;
    }
}

// ---------------------------------------------------------------------------
// Raw mma.sync (FA2-style) retention attention, windowed (W >= 320).
// ---------------------------------------------------------------------------
#define LQK 264                // bf16 elems per smem row (256 + 8 pad)
#define E_QH 0
#define E_QL 33792
#define E_KH 67584
#define E_KL 76032
#define E_VH 84480
#define E_VL 92928
#define SMEM_BYTES (101376 * 2)   // 202752 B

__device__ __forceinline__ void load_k32(uint32_t sb, int bn, int j0, int t) {
#pragma unroll
    for (int i = 0; i < 8; i++) {
        int idx = t + i * 256;
        int plane = idx >> 10, rem = idx & 1023;
        int row = rem >> 5, c = rem & 31;
        uint32_t dst = sb + (uint32_t)((plane ? E_KL : E_KH) + row * LQK + c * 8) * 2;
        const __nv_bfloat16* src = (plane ? g_Kl : g_Kh) +
                                   ((size_t)bn * S_LEN + j0 + row) * HID + c * 8;
        cpa16(dst, src);
    }
}
__device__ __forceinline__ void load_v32(uint32_t sb, int bn, int j0, int t) {
#pragma unroll
    for (int i = 0; i < 8; i++) {
        int idx = t + i * 256;
        int plane = idx >> 10, rem = idx & 1023;
        int row = rem >> 5, c = rem & 31;
        uint32_t dst = sb + (uint32_t)((plane ? E_VL : E_VH) + row * LQK + c * 8) * 2;
        const __nv_bfloat16* src = (plane ? g_Vl : g_Vh) +
                                   ((size_t)bn * S_LEN + j0 + row) * HID + c * 8;
        cpa16(dst, src);
    }
}

__global__ void __launch_bounds__(256, 1) attn_kernel(float* __restrict__ out) {
    extern __shared__ __align__(128) __nv_bfloat16 smattn[];
    uint32_t sb = smem_u32(smattn);
    int t = threadIdx.x, wid = t >> 5, l = t & 31;

    int qt = 15 - (blockIdx.x >> 4);   // heavy q-tiles first
    int bn = blockIdx.x & 15;
    int q0 = qt * 128;
    int jlo = max(0, qt * 4 - 10);     // window: drop d >= 321 (gamma^321 ~ 3.7e-5; xpos damps further)
    int jhi = qt * 4 + 3;

#pragma unroll
    for (int i = 0; i < 32; i++) {
        int idx = t + i * 256;
        int plane = idx >> 12, rem = idx & 4095;
        int row = rem >> 5, c = rem & 31;
        uint32_t dst = sb + (uint32_t)((plane ? E_QL : E_QH) + row * LQK + c * 8) * 2;
        const __nv_bfloat16* src = (plane ? g_Ql : g_Qh) +
                                   ((size_t)bn * S_LEN + q0 + row) * HID + c * 8;
        cpa16(dst, src);
    }
    load_k32(sb, bn, jlo * 32, t);
    load_v32(sb, bn, jlo * 32, t);
    CPA_COMMIT();

    int rowA = (l & 7) + ((l >> 3) & 1) * 8;
    int colA = (l >> 4) * 8;
    int rowK = (l & 7) + ((l >> 4) & 1) * 8;
    int colK = ((l >> 3) & 1) * 8;

    uint32_t qh_b = sb + (uint32_t)(E_QH + (wid * 16 + rowA) * LQK + colA) * 2;
    uint32_t ql_b = sb + (uint32_t)(E_QL + (wid * 16 + rowA) * LQK + colA) * 2;
    uint32_t kh_b = sb + (uint32_t)(E_KH + rowK * LQK + colK) * 2;
    uint32_t kl_b = sb + (uint32_t)(E_KL + rowK * LQK + colK) * 2;
    uint32_t vh_b = sb + (uint32_t)(E_VH + rowA * LQK + colA) * 2;
    uint32_t vl_b = sb + (uint32_t)(E_VL + rowA * LQK + colA) * 2;

    float o[32][4];
#pragma unroll
    for (int i = 0; i < 32; i++)
#pragma unroll
        for (int j = 0; j < 4; j++) o[i][j] = 0.f;

    CPA_WAIT(0);
    __syncthreads();

    int r0g = q0 + wid * 16 + (l >> 2);

    for (int kt = jlo; kt <= jhi; kt++) {
        int j0 = kt * 32;

        float sa[4][4];
#pragma unroll
        for (int i = 0; i < 4; i++)
#pragma unroll
            for (int j = 0; j < 4; j++) sa[i][j] = 0.f;

#pragma unroll 4
        for (int kc = 0; kc < 16; kc++) {
            uint32_t aH[4], aL[4], bh[8], bl[8];
            ldsm4(aH, qh_b + kc * 32);
            ldsm4(aL, ql_b + kc * 32);
            ldsm4(bh,     kh_b + kc * 32);
            ldsm4(bh + 4, kh_b + 16 * LQK * 2 + kc * 32);
            ldsm4(bl,     kl_b + kc * 32);
            ldsm4(bl + 4, kl_b + 16 * LQK * 2 + kc * 32);
#pragma unroll
            for (int tt = 0; tt < 4; tt++) {
                mma16816(sa[tt], aH, bh + tt * 2);
                mma16816(sa[tt], aH, bl + tt * 2);
                mma16816(sa[tt], aL, bh + tt * 2);
            }
        }
        __syncthreads();

        if (kt < jhi) { load_k32(sb, bn, j0 + 32, t); CPA_COMMIT(); }

        uint32_t pH[2][4], pL[2][4];
#pragma unroll
        for (int tt = 0; tt < 4; tt++) {
            int c0 = j0 + tt * 8 + 2 * (l & 3);
            int d = r0g - c0;
            float e0 = exp2f((float)d * L2G);
            float e8 = e0 * G8C;
            float p0 = (d >= 0)  ? sa[tt][0] * e0 : 0.f;
            float p1 = (d >= 1)  ? sa[tt][1] * (e0 * IGAM) : 0.f;
            float p2 = (d >= -8) ? sa[tt][2] * e8 : 0.f;
            float p3 = (d >= -7) ? sa[tt][3] * (e8 * IGAM) : 0.f;
            uint32_t h01, l01, h23, l23;
            split2(p0, p1, h01, l01);
            split2(p2, p3, h23, l23);
            int c2 = tt >> 1, jj = tt & 1;
            pH[c2][2 * jj + 0] = h01;  pH[c2][2 * jj + 1] = h23;
            pL[c2][2 * jj + 0] = l01;  pL[c2][2 * jj + 1] = l23;
        }

        if (kt < jhi) { CPA_WAIT(1); } else { CPA_WAIT(0); }
        __syncthreads();

#pragma unroll
        for (int c2 = 0; c2 < 2; c2++) {
#pragma unroll
            for (int nb = 0; nb < 16; nb++) {
                uint32_t bh[4], bl[4];
                ldsm4t(bh, vh_b + c2 * 16 * LQK * 2 + nb * 32);
                ldsm4t(bl, vl_b + c2 * 16 * LQK * 2 + nb * 32);
                mma16816(o[2 * nb],     pH[c2], bh);
                mma16816(o[2 * nb],     pH[c2], bl);
                mma16816(o[2 * nb],     pL[c2], bh);
                mma16816(o[2 * nb + 1], pH[c2], bh + 2);
                mma16816(o[2 * nb + 1], pH[c2], bl + 2);
                mma16816(o[2 * nb + 1], pL[c2], bh + 2);
            }
        }
        __syncthreads();

        if (kt < jhi) {
            load_v32(sb, bn, j0 + 32, t);      // V(kt+1)
            CPA_COMMIT();
            CPA_WAIT(1);                       // K(kt+1) done
        }
        __syncthreads();
    }

    float* ob = out + ((size_t)bn * S_LEN + r0g) * HID + 2 * (l & 3);
#pragma unroll
    for (int tt = 0; tt < 32; tt++) {
        *(float2*)(ob + tt * 8)           = make_float2(o[tt][0], o[tt][1]);
        *(float2*)(ob + 8 * HID + tt * 8) = make_float2(o[tt][2], o[tt][3]);
    }
}

// ---------------------------------------------------------------------------
extern "C" void kernel_launch(void* const* d_in, const int* in_sizes, int n_in,
                              void* d_out, int out_size) {
    const float* X  = (const float*)d_in[0];
    const float* Wq = (const float*)d_in[1];
    const float* Wk = (const float*)d_in[2];
    const float* Wv = (const float*)d_in[3];
    float* out = (float*)d_out;

    tab_kernel<<<(S_LEN * 128 + 255) / 256, 256>>>();
    xsplit_kernel<<<(M_ROWS * HID / 4) / 256, 256>>>(X);
    wsplit_kernel<<<3 * HID * HID / 2 / 256, 256>>>(Wq, Wk, Wv);

    cudaFuncSetAttribute(proj_kernel, cudaFuncAttributeMaxDynamicSharedMemorySize, PROJ_SMEM);
    proj_kernel<<<dim3(M_ROWS / 128, 3), 512, PROJ_SMEM>>>();

    cudaFuncSetAttribute(attn_kernel, cudaFuncAttributeMaxDynamicSharedMemorySize, SMEM_BYTES);
    attn_kernel<<<16 * BN, 256, SMEM_BYTES>>>(out);
}

// round 10
// speedup vs baseline: 6.6423x; 1.0608x over previous
#include <cuda_runtime.h>
#include <cuda_bf16.h>
#include <math.h>
#include <stdint.h>

#define S_LEN 2048
#define HID   256
#define BN    16
#define M_ROWS (BN * S_LEN)   // 32768

#define L2G  (-0.04580369f)              // log2(0.96875)
#define IGAM (1.03225806451612903f)      // 1/0.96875
#define G8C  (0.775700596198439598f)     // 0.96875^8 (exact)

// ---------------------------------------------------------------------------
// Device-global scratch (bf16 hi/lo splits)
// ---------------------------------------------------------------------------
__device__ __align__(256) __nv_bfloat16 g_Xh[(size_t)M_ROWS * HID];
__device__ __align__(256) __nv_bfloat16 g_Xl[(size_t)M_ROWS * HID];
__device__ __align__(256) __nv_bfloat16 g_Wh[3 * HID * HID];
__device__ __align__(256) __nv_bfloat16 g_Wl[3 * HID * HID];
__device__ __align__(256) __nv_bfloat16 g_Qh[(size_t)M_ROWS * HID];
__device__ __align__(256) __nv_bfloat16 g_Ql[(size_t)M_ROWS * HID];
__device__ __align__(256) __nv_bfloat16 g_Kh[(size_t)M_ROWS * HID];
__device__ __align__(256) __nv_bfloat16 g_Kl[(size_t)M_ROWS * HID];
__device__ __align__(256) __nv_bfloat16 g_Vh[(size_t)M_ROWS * HID];
__device__ __align__(256) __nv_bfloat16 g_Vl[(size_t)M_ROWS * HID];
__device__ float4 g_tab[S_LEN * 128];   // {sin, cos, scale, 1/scale}

// ---------------------------------------------------------------------------
// helpers
// ---------------------------------------------------------------------------
__device__ __forceinline__ uint32_t smem_u32(const void* p) {
    uint32_t a;
    asm("{ .reg .u64 t; cvta.to.shared.u64 t, %1; cvt.u32.u64 %0, t; }" : "=r"(a) : "l"(p));
    return a;
}
__device__ __forceinline__ void cpa16(uint32_t dst, const void* src) {
    asm volatile("cp.async.cg.shared.global [%0], [%1], 16;" :: "r"(dst), "l"(src));
}
#define CPA_COMMIT() asm volatile("cp.async.commit_group;" ::: "memory")
#define CPA_WAIT(n)  asm volatile("cp.async.wait_group %0;" :: "n"(n) : "memory")

__device__ __forceinline__ void ldsm4(uint32_t* r, uint32_t a) {
    asm volatile("ldmatrix.sync.aligned.m8n8.x4.shared.b16 {%0,%1,%2,%3}, [%4];"
                 : "=r"(r[0]), "=r"(r[1]), "=r"(r[2]), "=r"(r[3]) : "r"(a));
}
__device__ __forceinline__ void ldsm4t(uint32_t* r, uint32_t a) {
    asm volatile("ldmatrix.sync.aligned.m8n8.x4.trans.shared.b16 {%0,%1,%2,%3}, [%4];"
                 : "=r"(r[0]), "=r"(r[1]), "=r"(r[2]), "=r"(r[3]) : "r"(a));
}
__device__ __forceinline__ void mma16816(float* c, const uint32_t* a, const uint32_t* b) {
    asm volatile("mma.sync.aligned.m16n8k16.row.col.f32.bf16.bf16.f32 "
                 "{%0,%1,%2,%3}, {%4,%5,%6,%7}, {%8,%9}, {%0,%1,%2,%3};"
                 : "+f"(c[0]), "+f"(c[1]), "+f"(c[2]), "+f"(c[3])
                 : "r"(a[0]), "r"(a[1]), "r"(a[2]), "r"(a[3]), "r"(b[0]), "r"(b[1]));
}
__device__ __forceinline__ void split2(float a, float b, uint32_t& h, uint32_t& l) {
    __nv_bfloat162 hh = __floats2bfloat162_rn(a, b);
    __nv_bfloat162 ll = __floats2bfloat162_rn(a - __bfloat162float(hh.x),
                                              b - __bfloat162float(hh.y));
    h = *(uint32_t*)&hh;
    l = *(uint32_t*)&ll;
}

// ---------------------------------------------------------------------------
// xpos table
// ---------------------------------------------------------------------------
__global__ void tab_kernel() {
    int idx = blockIdx.x * 256 + threadIdx.x;
    if (idx >= S_LEN * 128) return;
    int s = idx >> 7, i = idx & 127;
    float inv_freq = (float)exp2(-(double)i * (13.287712379549449 / 128.0));
    float sn, cs;
    sincosf((float)s * inv_freq, &sn, &cs);
    float base  = ((float)(2 * i) + 102.4f) / 358.4f;
    float scale = exp2f(log2f(base) * ((float)s * (1.0f / 512.0f)));
    g_tab[idx] = make_float4(sn, cs, scale, 1.0f / scale);
}

// ---------------------------------------------------------------------------
// X split: fp32 -> bf16 hi/lo
// ---------------------------------------------------------------------------
__global__ void xsplit_kernel(const float* __restrict__ X) {
    size_t i = ((size_t)blockIdx.x * 256 + threadIdx.x) * 4;
    float4 v = *(const float4*)(X + i);
    uint2 hw, lw;
    split2(v.x, v.y, hw.x, lw.x);
    split2(v.z, v.w, hw.y, lw.y);
    *(uint2*)(g_Xh + i) = hw;
    *(uint2*)(g_Xl + i) = lw;
}

// W split: 3 x 256 x 256
__global__ void wsplit_kernel(const float* __restrict__ Wq,
                              const float* __restrict__ Wk,
                              const float* __restrict__ Wv) {
    int idx = blockIdx.x * 256 + threadIdx.x;
    int mode = idx >> 15, pos = (idx & 32767) * 2;
    const float* W = (mode == 0) ? Wq : (mode == 1) ? Wk : Wv;
    float a = W[pos], b = W[pos + 1];
    uint32_t h, l;
    split2(a, b, h, l);
    *(uint32_t*)(g_Wh + mode * 65536 + pos) = h;
    *(uint32_t*)(g_Wl + mode * 65536 + pos) = l;
}

// ---------------------------------------------------------------------------
// Tensor-core QKV projection (split-3 bf16 mma.sync) + fused xpos epilogue.
// grid: (2 n-halves, 3 modes, 256 row-tiles) -- row slowest so the 6 CTAs
// sharing an X row-tile dispatch adjacently (L2 reuse).
// CTA: 256 threads (8 warps x 16 rows), 128 rows x 128 cols.
// K=256 in 8 chunks of 32, double-buffered cp.async, 74KB smem -> 2 CTAs/SM.
// ---------------------------------------------------------------------------
#define LX 40      // X smem row stride (32+8) bf16
#define LW 136     // W smem row stride (128+8) bf16
#define P_XH 0
#define P_XL 5120      // 128*40
#define P_WH 10240
#define P_WL 14592     // 10240 + 32*136
#define PCHUNK 18944   // 14592 + 32*136
#define PROJ_SMEM (PCHUNK * 2 * 2)   // 75776 B

__device__ __forceinline__ void proj_load(uint32_t sb, int buf, int row0, int mode,
                                          int nh, int k0, int t) {
    uint32_t b0 = (uint32_t)(buf * PCHUNK);
    // X: 2 planes x 128 rows x 4 16B-units = 1024 units
#pragma unroll
    for (int i = 0; i < 4; i++) {
        int idx = t + i * 256;
        int plane = idx >> 9, rem = idx & 511;
        int row = rem >> 2, c = rem & 3;
        uint32_t dst = sb + (b0 + (plane ? P_XL : P_XH) + row * LX + c * 8) * 2;
        const __nv_bfloat16* src = (plane ? g_Xl : g_Xh) +
                                   ((size_t)(row0 + row)) * HID + k0 + c * 8;
        cpa16(dst, src);
    }
    // W: 2 planes x 32 rows x 16 16B-units = 1024 units
#pragma unroll
    for (int i = 0; i < 4; i++) {
        int idx = t + i * 256;
        int plane = idx >> 9, rem = idx & 511;
        int row = rem >> 4, c = rem & 15;
        uint32_t dst = sb + (b0 + (plane ? P_WL : P_WH) + row * LW + c * 8) * 2;
        const __nv_bfloat16* src = (plane ? g_Wl : g_Wh) +
                                   mode * 65536 + (k0 + row) * HID + nh * 128 + c * 8;
        cpa16(dst, src);
    }
}

__global__ void __launch_bounds__(256, 2) proj_kernel() {
    extern __shared__ __align__(128) __nv_bfloat16 smproj[];
    uint32_t sb = smem_u32(smproj);
    int t = threadIdx.x, wid = t >> 5, l = t & 31;
    int nh   = blockIdx.x;          // n half (128 cols)
    int mode = blockIdx.y;
    int row0 = blockIdx.z * 128;

    int rowA = (l & 7) + ((l >> 3) & 1) * 8;
    int colA = (l >> 4) * 8;

    float o[16][4];
#pragma unroll
    for (int i = 0; i < 16; i++)
#pragma unroll
        for (int j = 0; j < 4; j++) o[i][j] = 0.f;

    proj_load(sb, 0, row0, mode, nh, 0, t);
    CPA_COMMIT();

    for (int ch = 0; ch < 8; ch++) {
        int buf = ch & 1;
        if (ch < 7) { proj_load(sb, 1 - buf, row0, mode, nh, (ch + 1) * 32, t); CPA_COMMIT(); CPA_WAIT(1); }
        else        { CPA_WAIT(0); }
        __syncthreads();

        uint32_t b0 = (uint32_t)(buf * PCHUNK);
        uint32_t xh_b = sb + (b0 + P_XH + (wid * 16 + rowA) * LX + colA) * 2;
        uint32_t xl_b = sb + (b0 + P_XL + (wid * 16 + rowA) * LX + colA) * 2;
        uint32_t wh_b = sb + (b0 + P_WH + rowA * LW + colA) * 2;
        uint32_t wl_b = sb + (b0 + P_WL + rowA * LW + colA) * 2;

#pragma unroll
        for (int ks = 0; ks < 2; ks++) {
            uint32_t aH[4], aL[4];
            ldsm4(aH, xh_b + ks * 32);
            ldsm4(aL, xl_b + ks * 32);
#pragma unroll
            for (int nb = 0; nb < 8; nb++) {
                uint32_t bh[4], bl[4];
                ldsm4t(bh, wh_b + ks * 16 * LW * 2 + nb * 32);
                ldsm4t(bl, wl_b + ks * 16 * LW * 2 + nb * 32);
                mma16816(o[2 * nb],     aH, bh);
                mma16816(o[2 * nb],     aH, bl);
                mma16816(o[2 * nb],     aL, bh);
                mma16816(o[2 * nb + 1], aH, bh + 2);
                mma16816(o[2 * nb + 1], aH, bl + 2);
                mma16816(o[2 * nb + 1], aL, bh + 2);
            }
        }
        __syncthreads();
    }

    // ---- epilogue: optional xpos rotation, split, store ----
    __nv_bfloat16* oh = (mode == 0) ? g_Qh : (mode == 1) ? g_Kh : g_Vh;
    __nv_bfloat16* ol = (mode == 0) ? g_Ql : (mode == 1) ? g_Kl : g_Vl;
    int r1 = row0 + wid * 16 + (l >> 2);
    int r2 = r1 + 8;
    int s1 = r1 & (S_LEN - 1), s2 = r2 & (S_LEN - 1);

#pragma unroll
    for (int nb = 0; nb < 16; nb++) {
        int col = nh * 128 + nb * 8 + 2 * (l & 3);
        float a0 = o[nb][0], a1 = o[nb][1];
        float b0 = o[nb][2], b1 = o[nb][3];
        if (mode != 2) {
            float4 t1 = g_tab[s1 * 128 + (col >> 1)];
            float4 t2 = g_tab[s2 * 128 + (col >> 1)];
            float sc1 = (mode == 0) ? t1.z : t1.w;
            float sc2 = (mode == 0) ? t2.z : t2.w;
            float sn1 = t1.x * sc1, cs1 = t1.y * sc1;
            float sn2 = t2.x * sc2, cs2 = t2.y * sc2;
            float n0 = a0 * cs1 - a1 * sn1;
            float n1 = a1 * cs1 + a0 * sn1;
            float m0 = b0 * cs2 - b1 * sn2;
            float m1 = b1 * cs2 + b0 * sn2;
            a0 = n0; a1 = n1; b0 = m0; b1 = m1;
        }
        uint32_t h1, l1, h2, l2;
        split2(a0, a1, h1, l1);
        split2(b0, b1, h2, l2);
        *(uint32_t*)(oh + (size_t)r1 * HID + col) = h1;
        *(uint32_t*)(ol + (size_t)r1 * HID + col) = l1;
        *(uint32_t*)(oh + (size_t)r2 * HID + col) = h2;
        *(uint32_t*)(ol + (size_t)r2 * HID + col) = l2;
    }
}

// ---------------------------------------------------------------------------
// Raw mma.sync (FA2-style) retention attention, windowed (W >= 320).
// ---------------------------------------------------------------------------
#define LQK 264                // bf16 elems per smem row (256 + 8 pad)
#define E_QH 0
#define E_QL 33792
#define E_KH 67584
#define E_KL 76032
#define E_VH 84480
#define E_VL 92928
#define SMEM_BYTES (101376 * 2)   // 202752 B

__device__ __forceinline__ void load_k32(uint32_t sb, int bn, int j0, int t) {
#pragma unroll
    for (int i = 0; i < 8; i++) {
        int idx = t + i * 256;
        int plane = idx >> 10, rem = idx & 1023;
        int row = rem >> 5, c = rem & 31;
        uint32_t dst = sb + (uint32_t)((plane ? E_KL : E_KH) + row * LQK + c * 8) * 2;
        const __nv_bfloat16* src = (plane ? g_Kl : g_Kh) +
                                   ((size_t)bn * S_LEN + j0 + row) * HID + c * 8;
        cpa16(dst, src);
    }
}
__device__ __forceinline__ void load_v32(uint32_t sb, int bn, int j0, int t) {
#pragma unroll
    for (int i = 0; i < 8; i++) {
        int idx = t + i * 256;
        int plane = idx >> 10, rem = idx & 1023;
        int row = rem >> 5, c = rem & 31;
        uint32_t dst = sb + (uint32_t)((plane ? E_VL : E_VH) + row * LQK + c * 8) * 2;
        const __nv_bfloat16* src = (plane ? g_Vl : g_Vh) +
                                   ((size_t)bn * S_LEN + j0 + row) * HID + c * 8;
        cpa16(dst, src);
    }
}

__global__ void __launch_bounds__(256, 1) attn_kernel(float* __restrict__ out) {
    extern __shared__ __align__(128) __nv_bfloat16 smattn[];
    uint32_t sb = smem_u32(smattn);
    int t = threadIdx.x, wid = t >> 5, l = t & 31;

    int qt = 15 - (blockIdx.x >> 4);   // heavy q-tiles first
    int bn = blockIdx.x & 15;
    int q0 = qt * 128;
    int jlo = max(0, qt * 4 - 10);     // window: drop d >= 321 (gamma^321 ~ 3.7e-5)
    int jhi = qt * 4 + 3;

#pragma unroll
    for (int i = 0; i < 32; i++) {
        int idx = t + i * 256;
        int plane = idx >> 12, rem = idx & 4095;
        int row = rem >> 5, c = rem & 31;
        uint32_t dst = sb + (uint32_t)((plane ? E_QL : E_QH) + row * LQK + c * 8) * 2;
        const __nv_bfloat16* src = (plane ? g_Ql : g_Qh) +
                                   ((size_t)bn * S_LEN + q0 + row) * HID + c * 8;
        cpa16(dst, src);
    }
    load_k32(sb, bn, jlo * 32, t);
    load_v32(sb, bn, jlo * 32, t);
    CPA_COMMIT();

    int rowA = (l & 7) + ((l >> 3) & 1) * 8;
    int colA = (l >> 4) * 8;
    int rowK = (l & 7) + ((l >> 4) & 1) * 8;
    int colK = ((l >> 3) & 1) * 8;

    uint32_t qh_b = sb + (uint32_t)(E_QH + (wid * 16 + rowA) * LQK + colA) * 2;
    uint32_t ql_b = sb + (uint32_t)(E_QL + (wid * 16 + rowA) * LQK + colA) * 2;
    uint32_t kh_b = sb + (uint32_t)(E_KH + rowK * LQK + colK) * 2;
    uint32_t kl_b = sb + (uint32_t)(E_KL + rowK * LQK + colK) * 2;
    uint32_t vh_b = sb + (uint32_t)(E_VH + rowA * LQK + colA) * 2;
    uint32_t vl_b = sb + (uint32_t)(E_VL + rowA * LQK + colA) * 2;

    float o[32][4];
#pragma unroll
    for (int i = 0; i < 32; i++)
#pragma unroll
        for (int j = 0; j < 4; j++) o[i][j] = 0.f;

    CPA_WAIT(0);
    __syncthreads();

    int r0g = q0 + wid * 16 + (l >> 2);

    for (int kt = jlo; kt <= jhi; kt++) {
        int j0 = kt * 32;

        float sa[4][4];
#pragma unroll
        for (int i = 0; i < 4; i++)
#pragma unroll
            for (int j = 0; j < 4; j++) sa[i][j] = 0.f;

#pragma unroll 4
        for (int kc = 0; kc < 16; kc++) {
            uint32_t aH[4], aL[4], bh[8], bl[8];
            ldsm4(aH, qh_b + kc * 32);
            ldsm4(aL, ql_b + kc * 32);
            ldsm4(bh,     kh_b + kc * 32);
            ldsm4(bh + 4, kh_b + 16 * LQK * 2 + kc * 32);
            ldsm4(bl,     kl_b + kc * 32);
            ldsm4(bl + 4, kl_b + 16 * LQK * 2 + kc * 32);
#pragma unroll
            for (int tt = 0; tt < 4; tt++) {
                mma16816(sa[tt], aH, bh + tt * 2);
                mma16816(sa[tt], aH, bl + tt * 2);
                mma16816(sa[tt], aL, bh + tt * 2);
            }
        }
        __syncthreads();

        if (kt < jhi) { load_k32(sb, bn, j0 + 32, t); CPA_COMMIT(); }

        uint32_t pH[2][4], pL[2][4];
#pragma unroll
        for (int tt = 0; tt < 4; tt++) {
            int c0 = j0 + tt * 8 + 2 * (l & 3);
            int d = r0g - c0;
            float e0 = exp2f((float)d * L2G);
            float e8 = e0 * G8C;
            float p0 = (d >= 0)  ? sa[tt][0] * e0 : 0.f;
            float p1 = (d >= 1)  ? sa[tt][1] * (e0 * IGAM) : 0.f;
            float p2 = (d >= -8) ? sa[tt][2] * e8 : 0.f;
            float p3 = (d >= -7) ? sa[tt][3] * (e8 * IGAM) : 0.f;
            uint32_t h01, l01, h23, l23;
            split2(p0, p1, h01, l01);
            split2(p2, p3, h23, l23);
            int c2 = tt >> 1, jj = tt & 1;
            pH[c2][2 * jj + 0] = h01;  pH[c2][2 * jj + 1] = h23;
            pL[c2][2 * jj + 0] = l01;  pL[c2][2 * jj + 1] = l23;
        }

        if (kt < jhi) { CPA_WAIT(1); } else { CPA_WAIT(0); }
        __syncthreads();

#pragma unroll
        for (int c2 = 0; c2 < 2; c2++) {
#pragma unroll
            for (int nb = 0; nb < 16; nb++) {
                uint32_t bh[4], bl[4];
                ldsm4t(bh, vh_b + c2 * 16 * LQK * 2 + nb * 32);
                ldsm4t(bl, vl_b + c2 * 16 * LQK * 2 + nb * 32);
                mma16816(o[2 * nb],     pH[c2], bh);
                mma16816(o[2 * nb],     pH[c2], bl);
                mma16816(o[2 * nb],     pL[c2], bh);
                mma16816(o[2 * nb + 1], pH[c2], bh + 2);
                mma16816(o[2 * nb + 1], pH[c2], bl + 2);
                mma16816(o[2 * nb + 1], pL[c2], bh + 2);
            }
        }
        __syncthreads();

        if (kt < jhi) {
            load_v32(sb, bn, j0 + 32, t);      // V(kt+1)
            CPA_COMMIT();
            CPA_WAIT(1);                       // K(kt+1) done
        }
        __syncthreads();
    }

    float* ob = out + ((size_t)bn * S_LEN + r0g) * HID + 2 * (l & 3);
#pragma unroll
    for (int tt = 0; tt < 32; tt++) {
        *(float2*)(ob + tt * 8)           = make_float2(o[tt][0], o[tt][1]);
        *(float2*)(ob + 8 * HID + tt * 8) = make_float2(o[tt][2], o[tt][3]);
    }
}

// ---------------------------------------------------------------------------
extern "C" void kernel_launch(void* const* d_in, const int* in_sizes, int n_in,
                              void* d_out, int out_size) {
    const float* X  = (const float*)d_in[0];
    const float* Wq = (const float*)d_in[1];
    const float* Wk = (const float*)d_in[2];
    const float* Wv = (const float*)d_in[3];
    float* out = (float*)d_out;

    tab_kernel<<<(S_LEN * 128 + 255) / 256, 256>>>();
    xsplit_kernel<<<(M_ROWS * HID / 4) / 256, 256>>>(X);
    wsplit_kernel<<<3 * HID * HID / 2 / 256, 256>>>(Wq, Wk, Wv);

    cudaFuncSetAttribute(proj_kernel, cudaFuncAttributeMaxDynamicSharedMemorySize, PROJ_SMEM);
    proj_kernel<<<dim3(2, 3, 256), 256, PROJ_SMEM>>>();

    cudaFuncSetAttribute(attn_kernel, cudaFuncAttributeMaxDynamicSharedMemorySize, SMEM_BYTES);
    attn_kernel<<<16 * BN, 256, SMEM_BYTES>>>(out);
}

// round 11
// speedup vs baseline: 7.1216x; 1.0722x over previous
#include <cuda_runtime.h>
#include <cuda_bf16.h>
#include <math.h>
#include <stdint.h>

#define S_LEN 2048
#define HID   256
#define BN    16
#define M_ROWS (BN * S_LEN)   // 32768

#define L2G  (-0.04580369f)              // log2(0.96875)
#define IGAM (1.03225806451612903f)      // 1/0.96875
#define G8C  (0.775700596198439598f)     // 0.96875^8 (exact)

// ---------------------------------------------------------------------------
// Device-global scratch (bf16 hi/lo splits)
// ---------------------------------------------------------------------------
__device__ __align__(256) __nv_bfloat16 g_Xh[(size_t)M_ROWS * HID];
__device__ __align__(256) __nv_bfloat16 g_Xl[(size_t)M_ROWS * HID];
__device__ __align__(256) __nv_bfloat16 g_Wh[3 * HID * HID];
__device__ __align__(256) __nv_bfloat16 g_Wl[3 * HID * HID];
__device__ __align__(256) __nv_bfloat16 g_Qh[(size_t)M_ROWS * HID];
__device__ __align__(256) __nv_bfloat16 g_Ql[(size_t)M_ROWS * HID];
__device__ __align__(256) __nv_bfloat16 g_Kh[(size_t)M_ROWS * HID];
__device__ __align__(256) __nv_bfloat16 g_Kl[(size_t)M_ROWS * HID];
__device__ __align__(256) __nv_bfloat16 g_Vh[(size_t)M_ROWS * HID];
__device__ __align__(256) __nv_bfloat16 g_Vl[(size_t)M_ROWS * HID];
__device__ float4 g_tab[S_LEN * 128];   // {sin, cos, scale, 1/scale}

// ---------------------------------------------------------------------------
// helpers
// ---------------------------------------------------------------------------
__device__ __forceinline__ uint32_t smem_u32(const void* p) {
    uint32_t a;
    asm("{ .reg .u64 t; cvta.to.shared.u64 t, %1; cvt.u32.u64 %0, t; }" : "=r"(a) : "l"(p));
    return a;
}
__device__ __forceinline__ void cpa16(uint32_t dst, const void* src) {
    asm volatile("cp.async.cg.shared.global [%0], [%1], 16;" :: "r"(dst), "l"(src));
}
#define CPA_COMMIT() asm volatile("cp.async.commit_group;" ::: "memory")
#define CPA_WAIT(n)  asm volatile("cp.async.wait_group %0;" :: "n"(n) : "memory")

__device__ __forceinline__ void ldsm4(uint32_t* r, uint32_t a) {
    asm volatile("ldmatrix.sync.aligned.m8n8.x4.shared.b16 {%0,%1,%2,%3}, [%4];"
                 : "=r"(r[0]), "=r"(r[1]), "=r"(r[2]), "=r"(r[3]) : "r"(a));
}
__device__ __forceinline__ void ldsm4t(uint32_t* r, uint32_t a) {
    asm volatile("ldmatrix.sync.aligned.m8n8.x4.trans.shared.b16 {%0,%1,%2,%3}, [%4];"
                 : "=r"(r[0]), "=r"(r[1]), "=r"(r[2]), "=r"(r[3]) : "r"(a));
}
__device__ __forceinline__ void mma16816(float* c, const uint32_t* a, const uint32_t* b) {
    asm volatile("mma.sync.aligned.m16n8k16.row.col.f32.bf16.bf16.f32 "
                 "{%0,%1,%2,%3}, {%4,%5,%6,%7}, {%8,%9}, {%0,%1,%2,%3};"
                 : "+f"(c[0]), "+f"(c[1]), "+f"(c[2]), "+f"(c[3])
                 : "r"(a[0]), "r"(a[1]), "r"(a[2]), "r"(a[3]), "r"(b[0]), "r"(b[1]));
}
__device__ __forceinline__ void split2(float a, float b, uint32_t& h, uint32_t& l) {
    __nv_bfloat162 hh = __floats2bfloat162_rn(a, b);
    __nv_bfloat162 ll = __floats2bfloat162_rn(a - __bfloat162float(hh.x),
                                              b - __bfloat162float(hh.y));
    h = *(uint32_t*)&hh;
    l = *(uint32_t*)&ll;
}

// ---------------------------------------------------------------------------
// Fused prep: X split (blocks 0..8191) | xpos table (8192..9215) | W split (9216..9599)
// ---------------------------------------------------------------------------
__global__ void prep_kernel(const float* __restrict__ X,
                            const float* __restrict__ Wq,
                            const float* __restrict__ Wk,
                            const float* __restrict__ Wv) {
    int b = blockIdx.x;
    if (b < 8192) {
        size_t i = ((size_t)b * 256 + threadIdx.x) * 4;
        float4 v = *(const float4*)(X + i);
        uint2 hw, lw;
        split2(v.x, v.y, hw.x, lw.x);
        split2(v.z, v.w, hw.y, lw.y);
        *(uint2*)(g_Xh + i) = hw;
        *(uint2*)(g_Xl + i) = lw;
    } else if (b < 9216) {
        int idx = (b - 8192) * 256 + threadIdx.x;
        int s = idx >> 7, i = idx & 127;
        float inv_freq = (float)exp2(-(double)i * (13.287712379549449 / 128.0));
        float sn, cs;
        sincosf((float)s * inv_freq, &sn, &cs);
        float base  = ((float)(2 * i) + 102.4f) / 358.4f;
        float scale = exp2f(log2f(base) * ((float)s * (1.0f / 512.0f)));
        g_tab[idx] = make_float4(sn, cs, scale, 1.0f / scale);
    } else {
        int idx = (b - 9216) * 256 + threadIdx.x;
        int mode = idx >> 15, pos = (idx & 32767) * 2;
        const float* W = (mode == 0) ? Wq : (mode == 1) ? Wk : Wv;
        float a = W[pos], c = W[pos + 1];
        uint32_t h, l;
        split2(a, c, h, l);
        *(uint32_t*)(g_Wh + mode * 65536 + pos) = h;
        *(uint32_t*)(g_Wl + mode * 65536 + pos) = l;
    }
}

// ---------------------------------------------------------------------------
// Tensor-core QKV projection (split-3 bf16 mma.sync) + fused xpos epilogue.
// grid: (2 n-halves, 3 modes, 256 row-tiles), row slowest (L2 reuse of X).
// CTA: 256 threads (8 warps x 16 rows), 128 rows x 128 cols.
// K=256 in 8 chunks of 32, RING-3 buffered cp.async (prefetch distance 2),
// 111 KB smem -> 2 CTAs/SM.
// ---------------------------------------------------------------------------
#define LX 40      // X smem row stride (32+8) bf16
#define LW 136     // W smem row stride (128+8) bf16
#define P_XH 0
#define P_XL 5120      // 128*40
#define P_WH 10240
#define P_WL 14592     // 10240 + 32*136
#define PCHUNK 18944   // 14592 + 32*136
#define NBUF 3
#define PROJ_SMEM (PCHUNK * NBUF * 2)   // 113664 B

__device__ __forceinline__ void proj_load(uint32_t sb, int buf, int row0, int mode,
                                          int nh, int k0, int t) {
    uint32_t b0 = (uint32_t)(buf * PCHUNK);
    // X: 2 planes x 128 rows x 4 16B-units = 1024 units
#pragma unroll
    for (int i = 0; i < 4; i++) {
        int idx = t + i * 256;
        int plane = idx >> 9, rem = idx & 511;
        int row = rem >> 2, c = rem & 3;
        uint32_t dst = sb + (b0 + (plane ? P_XL : P_XH) + row * LX + c * 8) * 2;
        const __nv_bfloat16* src = (plane ? g_Xl : g_Xh) +
                                   ((size_t)(row0 + row)) * HID + k0 + c * 8;
        cpa16(dst, src);
    }
    // W: 2 planes x 32 rows x 16 16B-units = 1024 units
#pragma unroll
    for (int i = 0; i < 4; i++) {
        int idx = t + i * 256;
        int plane = idx >> 9, rem = idx & 511;
        int row = rem >> 4, c = rem & 15;
        uint32_t dst = sb + (b0 + (plane ? P_WL : P_WH) + row * LW + c * 8) * 2;
        const __nv_bfloat16* src = (plane ? g_Wl : g_Wh) +
                                   mode * 65536 + (k0 + row) * HID + nh * 128 + c * 8;
        cpa16(dst, src);
    }
}

__global__ void __launch_bounds__(256, 2) proj_kernel() {
    extern __shared__ __align__(128) __nv_bfloat16 smproj[];
    uint32_t sb = smem_u32(smproj);
    int t = threadIdx.x, wid = t >> 5, l = t & 31;
    int nh   = blockIdx.x;          // n half (128 cols)
    int mode = blockIdx.y;
    int row0 = blockIdx.z * 128;

    int rowA = (l & 7) + ((l >> 3) & 1) * 8;
    int colA = (l >> 4) * 8;

    float o[16][4];
#pragma unroll
    for (int i = 0; i < 16; i++)
#pragma unroll
        for (int j = 0; j < 4; j++) o[i][j] = 0.f;

    proj_load(sb, 0, row0, mode, nh, 0, t);
    CPA_COMMIT();
    proj_load(sb, 1, row0, mode, nh, 32, t);
    CPA_COMMIT();

    for (int ch = 0; ch < 8; ch++) {
        int buf = ch % NBUF;
        if (ch + 2 < 8) {
            proj_load(sb, (ch + 2) % NBUF, row0, mode, nh, (ch + 2) * 32, t);
            CPA_COMMIT();
            CPA_WAIT(2);            // chunk ch's group done
        } else if (ch + 1 < 8) {
            CPA_WAIT(1);
        } else {
            CPA_WAIT(0);
        }
        __syncthreads();

        uint32_t b0 = (uint32_t)(buf * PCHUNK);
        uint32_t xh_b = sb + (b0 + P_XH + (wid * 16 + rowA) * LX + colA) * 2;
        uint32_t xl_b = sb + (b0 + P_XL + (wid * 16 + rowA) * LX + colA) * 2;
        uint32_t wh_b = sb + (b0 + P_WH + rowA * LW + colA) * 2;
        uint32_t wl_b = sb + (b0 + P_WL + rowA * LW + colA) * 2;

#pragma unroll
        for (int ks = 0; ks < 2; ks++) {
            uint32_t aH[4], aL[4];
            ldsm4(aH, xh_b + ks * 32);
            ldsm4(aL, xl_b + ks * 32);
#pragma unroll
            for (int nb = 0; nb < 8; nb++) {
                uint32_t bh[4], bl[4];
                ldsm4t(bh, wh_b + ks * 16 * LW * 2 + nb * 32);
                ldsm4t(bl, wl_b + ks * 16 * LW * 2 + nb * 32);
                mma16816(o[2 * nb],     aH, bh);
                mma16816(o[2 * nb],     aH, bl);
                mma16816(o[2 * nb],     aL, bh);
                mma16816(o[2 * nb + 1], aH, bh + 2);
                mma16816(o[2 * nb + 1], aH, bl + 2);
                mma16816(o[2 * nb + 1], aL, bh + 2);
            }
        }
        __syncthreads();            // buffer consumed before it is reloaded
    }

    // ---- epilogue: optional xpos rotation, split, store ----
    __nv_bfloat16* oh = (mode == 0) ? g_Qh : (mode == 1) ? g_Kh : g_Vh;
    __nv_bfloat16* ol = (mode == 0) ? g_Ql : (mode == 1) ? g_Kl : g_Vl;
    int r1 = row0 + wid * 16 + (l >> 2);
    int r2 = r1 + 8;
    int s1 = r1 & (S_LEN - 1), s2 = r2 & (S_LEN - 1);

#pragma unroll
    for (int nb = 0; nb < 16; nb++) {
        int col = nh * 128 + nb * 8 + 2 * (l & 3);
        float a0 = o[nb][0], a1 = o[nb][1];
        float b0 = o[nb][2], b1 = o[nb][3];
        if (mode != 2) {
            float4 t1 = g_tab[s1 * 128 + (col >> 1)];
            float4 t2 = g_tab[s2 * 128 + (col >> 1)];
            float sc1 = (mode == 0) ? t1.z : t1.w;
            float sc2 = (mode == 0) ? t2.z : t2.w;
            float sn1 = t1.x * sc1, cs1 = t1.y * sc1;
            float sn2 = t2.x * sc2, cs2 = t2.y * sc2;
            float n0 = a0 * cs1 - a1 * sn1;
            float n1 = a1 * cs1 + a0 * sn1;
            float m0 = b0 * cs2 - b1 * sn2;
            float m1 = b1 * cs2 + b0 * sn2;
            a0 = n0; a1 = n1; b0 = m0; b1 = m1;
        }
        uint32_t h1, l1, h2, l2;
        split2(a0, a1, h1, l1);
        split2(b0, b1, h2, l2);
        *(uint32_t*)(oh + (size_t)r1 * HID + col) = h1;
        *(uint32_t*)(ol + (size_t)r1 * HID + col) = l1;
        *(uint32_t*)(oh + (size_t)r2 * HID + col) = h2;
        *(uint32_t*)(ol + (size_t)r2 * HID + col) = l2;
    }
}

// ---------------------------------------------------------------------------
// Raw mma.sync (FA2-style) retention attention, windowed (W >= 256).
// ---------------------------------------------------------------------------
#define LQK 264                // bf16 elems per smem row (256 + 8 pad)
#define E_QH 0
#define E_QL 33792
#define E_KH 67584
#define E_KL 76032
#define E_VH 84480
#define E_VL 92928
#define SMEM_BYTES (101376 * 2)   // 202752 B

__device__ __forceinline__ void load_k32(uint32_t sb, int bn, int j0, int t) {
#pragma unroll
    for (int i = 0; i < 8; i++) {
        int idx = t + i * 256;
        int plane = idx >> 10, rem = idx & 1023;
        int row = rem >> 5, c = rem & 31;
        uint32_t dst = sb + (uint32_t)((plane ? E_KL : E_KH) + row * LQK + c * 8) * 2;
        const __nv_bfloat16* src = (plane ? g_Kl : g_Kh) +
                                   ((size_t)bn * S_LEN + j0 + row) * HID + c * 8;
        cpa16(dst, src);
    }
}
__device__ __forceinline__ void load_v32(uint32_t sb, int bn, int j0, int t) {
#pragma unroll
    for (int i = 0; i < 8; i++) {
        int idx = t + i * 256;
        int plane = idx >> 10, rem = idx & 1023;
        int row = rem >> 5, c = rem & 31;
        uint32_t dst = sb + (uint32_t)((plane ? E_VL : E_VH) + row * LQK + c * 8) * 2;
        const __nv_bfloat16* src = (plane ? g_Vl : g_Vh) +
                                   ((size_t)bn * S_LEN + j0 + row) * HID + c * 8;
        cpa16(dst, src);
    }
}

__global__ void __launch_bounds__(256, 1) attn_kernel(float* __restrict__ out) {
    extern __shared__ __align__(128) __nv_bfloat16 smattn[];
    uint32_t sb = smem_u32(smattn);
    int t = threadIdx.x, wid = t >> 5, l = t & 31;

    int qt = 15 - (blockIdx.x >> 4);   // heavy q-tiles first
    int bn = blockIdx.x & 15;
    int q0 = qt * 128;
    int jlo = max(0, qt * 4 - 8);      // window: drop d >= 257 (gamma^257 ~ 2.9e-4 worst row)
    int jhi = qt * 4 + 3;

#pragma unroll
    for (int i = 0; i < 32; i++) {
        int idx = t + i * 256;
        int plane = idx >> 12, rem = idx & 4095;
        int row = rem >> 5, c = rem & 31;
        uint32_t dst = sb + (uint32_t)((plane ? E_QL : E_QH) + row * LQK + c * 8) * 2;
        const __nv_bfloat16* src = (plane ? g_Ql : g_Qh) +
                                   ((size_t)bn * S_LEN + q0 + row) * HID + c * 8;
        cpa16(dst, src);
    }
    load_k32(sb, bn, jlo * 32, t);
    load_v32(sb, bn, jlo * 32, t);
    CPA_COMMIT();

    int rowA = (l & 7) + ((l >> 3) & 1) * 8;
    int colA = (l >> 4) * 8;
    int rowK = (l & 7) + ((l >> 4) & 1) * 8;
    int colK = ((l >> 3) & 1) * 8;

    uint32_t qh_b = sb + (uint32_t)(E_QH + (wid * 16 + rowA) * LQK + colA) * 2;
    uint32_t ql_b = sb + (uint32_t)(E_QL + (wid * 16 + rowA) * LQK + colA) * 2;
    uint32_t kh_b = sb + (uint32_t)(E_KH + rowK * LQK + colK) * 2;
    uint32_t kl_b = sb + (uint32_t)(E_KL + rowK * LQK + colK) * 2;
    uint32_t vh_b = sb + (uint32_t)(E_VH + rowA * LQK + colA) * 2;
    uint32_t vl_b = sb + (uint32_t)(E_VL + rowA * LQK + colA) * 2;

    float o[32][4];
#pragma unroll
    for (int i = 0; i < 32; i++)
#pragma unroll
        for (int j = 0; j < 4; j++) o[i][j] = 0.f;

    CPA_WAIT(0);
    __syncthreads();

    int r0g = q0 + wid * 16 + (l >> 2);

    for (int kt = jlo; kt <= jhi; kt++) {
        int j0 = kt * 32;

        float sa[4][4];
#pragma unroll
        for (int i = 0; i < 4; i++)
#pragma unroll
            for (int j = 0; j < 4; j++) sa[i][j] = 0.f;

#pragma unroll 4
        for (int kc = 0; kc < 16; kc++) {
            uint32_t aH[4], aL[4], bh[8], bl[8];
            ldsm4(aH, qh_b + kc * 32);
            ldsm4(aL, ql_b + kc * 32);
            ldsm4(bh,     kh_b + kc * 32);
            ldsm4(bh + 4, kh_b + 16 * LQK * 2 + kc * 32);
            ldsm4(bl,     kl_b + kc * 32);
            ldsm4(bl + 4, kl_b + 16 * LQK * 2 + kc * 32);
#pragma unroll
            for (int tt = 0; tt < 4; tt++) {
                mma16816(sa[tt], aH, bh + tt * 2);
                mma16816(sa[tt], aH, bl + tt * 2);
                mma16816(sa[tt], aL, bh + tt * 2);
            }
        }
        __syncthreads();

        if (kt < jhi) { load_k32(sb, bn, j0 + 32, t); CPA_COMMIT(); }

        uint32_t pH[2][4], pL[2][4];
#pragma unroll
        for (int tt = 0; tt < 4; tt++) {
            int c0 = j0 + tt * 8 + 2 * (l & 3);
            int d = r0g - c0;
            float e0 = exp2f((float)d * L2G);
            float e8 = e0 * G8C;
            float p0 = (d >= 0)  ? sa[tt][0] * e0 : 0.f;
            float p1 = (d >= 1)  ? sa[tt][1] * (e0 * IGAM) : 0.f;
            float p2 = (d >= -8) ? sa[tt][2] * e8 : 0.f;
            float p3 = (d >= -7) ? sa[tt][3] * (e8 * IGAM) : 0.f;
            uint32_t h01, l01, h23, l23;
            split2(p0, p1, h01, l01);
            split2(p2, p3, h23, l23);
            int c2 = tt >> 1, jj = tt & 1;
            pH[c2][2 * jj + 0] = h01;  pH[c2][2 * jj + 1] = h23;
            pL[c2][2 * jj + 0] = l01;  pL[c2][2 * jj + 1] = l23;
        }

        if (kt < jhi) { CPA_WAIT(1); } else { CPA_WAIT(0); }
        __syncthreads();

#pragma unroll
        for (int c2 = 0; c2 < 2; c2++) {
#pragma unroll
            for (int nb = 0; nb < 16; nb++) {
                uint32_t bh[4], bl[4];
                ldsm4t(bh, vh_b + c2 * 16 * LQK * 2 + nb * 32);
                ldsm4t(bl, vl_b + c2 * 16 * LQK * 2 + nb * 32);
                mma16816(o[2 * nb],     pH[c2], bh);
                mma16816(o[2 * nb],     pH[c2], bl);
                mma16816(o[2 * nb],     pL[c2], bh);
                mma16816(o[2 * nb + 1], pH[c2], bh + 2);
                mma16816(o[2 * nb + 1], pH[c2], bl + 2);
                mma16816(o[2 * nb + 1], pL[c2], bh + 2);
            }
        }
        __syncthreads();

        if (kt < jhi) {
            load_v32(sb, bn, j0 + 32, t);      // V(kt+1)
            CPA_COMMIT();
            CPA_WAIT(1);                       // K(kt+1) done
        }
        __syncthreads();
    }

    float* ob = out + ((size_t)bn * S_LEN + r0g) * HID + 2 * (l & 3);
#pragma unroll
    for (int tt = 0; tt < 32; tt++) {
        *(float2*)(ob + tt * 8)           = make_float2(o[tt][0], o[tt][1]);
        *(float2*)(ob + 8 * HID + tt * 8) = make_float2(o[tt][2], o[tt][3]);
    }
}

// ---------------------------------------------------------------------------
extern "C" void kernel_launch(void* const* d_in, const int* in_sizes, int n_in,
                              void* d_out, int out_size) {
    const float* X  = (const float*)d_in[0];
    const float* Wq = (const float*)d_in[1];
    const float* Wk = (const float*)d_in[2];
    const float* Wv = (const float*)d_in[3];
    float* out = (float*)d_out;

    prep_kernel<<<9600, 256>>>(X, Wq, Wk, Wv);

    cudaFuncSetAttribute(proj_kernel, cudaFuncAttributeMaxDynamicSharedMemorySize, PROJ_SMEM);
    proj_kernel<<<dim3(2, 3, 256), 256, PROJ_SMEM>>>();

    cudaFuncSetAttribute(attn_kernel, cudaFuncAttributeMaxDynamicSharedMemorySize, SMEM_BYTES);
    attn_kernel<<<16 * BN, 256, SMEM_BYTES>>>(out);
}

// round 12
// speedup vs baseline: 7.7099x; 1.0826x over previous
#include <cuda_runtime.h>
#include <cuda_bf16.h>
#include <math.h>
#include <stdint.h>

#define S_LEN 2048
#define HID   256
#define BN    16
#define M_ROWS (BN * S_LEN)   // 32768

#define L2G  (-0.04580369f)              // log2(0.96875)
#define IGAM (1.03225806451612903f)      // 1/0.96875
#define G8C  (0.775700596198439598f)     // 0.96875^8 (exact)

// ---------------------------------------------------------------------------
// Device-global scratch: PRE-SWIZZLED smem-image tiles.
// Image layout rule: within an image of row stride R bytes, the byte offset of
// (row, colb) is  row*R + (colb ^ ((row & 7) << 4)).  This permutes 16B units
// only within 128B lines (coalescing-safe) and makes ldmatrix conflict-free.
//   X images: [tile256][chunk4][plane2][128 rows x 128B]   (R=128)
//   W images: [mode3][nh2][chunk4][plane2][64 rows x 256B] (R=256)
//   Q/K/V images: [bn16][tile64][plane2][32 rows x 512B]   (R=512)
// ---------------------------------------------------------------------------
__device__ __align__(256) uint8_t g_Xi[33554432];
__device__ __align__(256) uint8_t g_Wi[786432];
__device__ __align__(256) uint8_t g_Qi[33554432];
__device__ __align__(256) uint8_t g_Ki[33554432];
__device__ __align__(256) uint8_t g_Vi[33554432];
__device__ float4 g_tab[S_LEN * 128];   // {sin, cos, scale, 1/scale}

// ---------------------------------------------------------------------------
// helpers
// ---------------------------------------------------------------------------
__device__ __forceinline__ uint32_t smem_u32(const void* p) {
    uint32_t a;
    asm("{ .reg .u64 t; cvta.to.shared.u64 t, %1; cvt.u32.u64 %0, t; }" : "=r"(a) : "l"(p));
    return a;
}
#define MBAR_INIT(mb, c) asm volatile("mbarrier.init.shared.b64 [%0], %1;" :: "r"(mb), "r"((uint32_t)(c)) : "memory")
#define MBAR_EXPECT(mb, bytes) \
    asm volatile("mbarrier.arrive.expect_tx.shared.b64 _, [%0], %1;" :: "r"(mb), "r"((uint32_t)(bytes)) : "memory")

__device__ __forceinline__ void bulk_g2s(uint32_t dst, const void* src, uint32_t bytes, uint32_t mbar) {
    asm volatile("cp.async.bulk.shared::cluster.global.mbarrier::complete_tx::bytes [%0], [%1], %2, [%3];"
                 :: "r"(dst), "l"(src), "r"(bytes), "r"(mbar) : "memory");
}
__device__ __forceinline__ void mbar_wait(uint32_t mb, uint32_t ph) {
    uint32_t done;
    asm volatile("{\n\t.reg .pred p;\n\tmbarrier.try_wait.parity.acquire.cta.shared::cta.b64 p, [%1], %2;\n\tselp.b32 %0, 1, 0, p;\n\t}"
                 : "=r"(done) : "r"(mb), "r"(ph) : "memory");
    if (!done) {
        asm volatile("{\n\t.reg .pred P1;\n\tWL%=:\n\tmbarrier.try_wait.parity.acquire.cta.shared::cta.b64 P1, [%0], %1, 0x989680;\n\t@P1 bra.uni WD%=;\n\tbra.uni WL%=;\n\tWD%=:\n\t}"
                     :: "r"(mb), "r"(ph) : "memory");
    }
}
__device__ __forceinline__ void ldsm4(uint32_t* r, uint32_t a) {
    asm volatile("ldmatrix.sync.aligned.m8n8.x4.shared.b16 {%0,%1,%2,%3}, [%4];"
                 : "=r"(r[0]), "=r"(r[1]), "=r"(r[2]), "=r"(r[3]) : "r"(a));
}
__device__ __forceinline__ void ldsm4t(uint32_t* r, uint32_t a) {
    asm volatile("ldmatrix.sync.aligned.m8n8.x4.trans.shared.b16 {%0,%1,%2,%3}, [%4];"
                 : "=r"(r[0]), "=r"(r[1]), "=r"(r[2]), "=r"(r[3]) : "r"(a));
}
__device__ __forceinline__ void mma16816(float* c, const uint32_t* a, const uint32_t* b) {
    asm volatile("mma.sync.aligned.m16n8k16.row.col.f32.bf16.bf16.f32 "
                 "{%0,%1,%2,%3}, {%4,%5,%6,%7}, {%8,%9}, {%0,%1,%2,%3};"
                 : "+f"(c[0]), "+f"(c[1]), "+f"(c[2]), "+f"(c[3])
                 : "r"(a[0]), "r"(a[1]), "r"(a[2]), "r"(a[3]), "r"(b[0]), "r"(b[1]));
}
__device__ __forceinline__ void split2(float a, float b, uint32_t& h, uint32_t& l) {
    __nv_bfloat162 hh = __floats2bfloat162_rn(a, b);
    __nv_bfloat162 ll = __floats2bfloat162_rn(a - __bfloat162float(hh.x),
                                              b - __bfloat162float(hh.y));
    h = *(uint32_t*)&hh;
    l = *(uint32_t*)&ll;
}

// ---------------------------------------------------------------------------
// Fused prep: X images (blocks 0..8191) | xpos table (8192..9215) | W images
// ---------------------------------------------------------------------------
__global__ void prep_kernel(const float* __restrict__ X,
                            const float* __restrict__ Wq,
                            const float* __restrict__ Wk,
                            const float* __restrict__ Wv) {
    int b = blockIdx.x;
    if (b < 8192) {
        size_t i = ((size_t)b * 256 + threadIdx.x) * 4;
        float4 v = *(const float4*)(X + i);
        uint2 hw, lw;
        split2(v.x, v.y, hw.x, lw.x);
        split2(v.z, v.w, hw.y, lw.y);
        int row = (int)(i >> 8), k0 = (int)(i & 255);
        int tile = row >> 7, r = row & 127;
        int chunk = k0 >> 6, kk = k0 & 63;
        uint32_t m = (uint32_t)((r & 7) << 4);
        uint32_t off = (uint32_t)(((tile * 4 + chunk) * 2) * 16384)
                     + (uint32_t)(r * 128) + (((uint32_t)(kk * 2)) ^ m);
        *(uint2*)(g_Xi + off)         = hw;
        *(uint2*)(g_Xi + off + 16384) = lw;
    } else if (b < 9216) {
        int idx = (b - 8192) * 256 + threadIdx.x;
        int s = idx >> 7, i = idx & 127;
        float inv_freq = (float)exp2(-(double)i * (13.287712379549449 / 128.0));
        float sn, cs;
        sincosf((float)s * inv_freq, &sn, &cs);
        float base  = ((float)(2 * i) + 102.4f) / 358.4f;
        float scale = exp2f(log2f(base) * ((float)s * (1.0f / 512.0f)));
        g_tab[idx] = make_float4(sn, cs, scale, 1.0f / scale);
    } else {
        int idx = (b - 9216) * 256 + threadIdx.x;
        int mode = idx >> 15, pos = (idx & 32767) * 2;
        const float* W = (mode == 0) ? Wq : (mode == 1) ? Wk : Wv;
        float a = W[pos], c = W[pos + 1];
        uint32_t h, l;
        split2(a, c, h, l);
        int k = pos >> 8, n = pos & 255;
        int nh = n >> 7, nn = n & 127;
        int chunk = k >> 6, kr = k & 63;
        uint32_t m = (uint32_t)((kr & 7) << 4);
        uint32_t off = (uint32_t)((((mode * 2 + nh) * 4 + chunk) * 2) * 16384)
                     + (uint32_t)(kr * 256) + (((uint32_t)(nn * 2)) ^ m);
        *(uint32_t*)(g_Wi + off)         = h;
        *(uint32_t*)(g_Wi + off + 16384) = l;
    }
}

// ---------------------------------------------------------------------------
// Tensor-core QKV projection: TMA-bulk staged, split-3 bf16 mma.sync,
// fused xpos epilogue writing Q/K/V smem-images.
// grid: (2 nh, 3 modes, 256 row-tiles). CTA 256 thr, 128 rows x 128 cols.
// K=256 in 4 chunks of 64, ring-3 bulk buffers (192 KB smem).
// ---------------------------------------------------------------------------
#define PROJ_SMEM 196608

__global__ void __launch_bounds__(256, 1) proj_kernel() {
    extern __shared__ __align__(128) uint8_t smp[];
    __shared__ __align__(8) uint64_t mbs[3];
    uint32_t sb = smem_u32(smp);
    int t = threadIdx.x, wid = t >> 5, l = t & 31;
    int nh   = blockIdx.x;
    int mode = blockIdx.y;

    if (t == 0) {
#pragma unroll
        for (int i = 0; i < 3; i++) MBAR_INIT(smem_u32(&mbs[i]), 1);
    }
    __syncthreads();

    const uint8_t* xsrc = g_Xi + (size_t)(blockIdx.z * 4) * 32768;
    const uint8_t* wsrc = g_Wi + (size_t)((mode * 2 + nh) * 4) * 32768;

    if (t == 0) {
#pragma unroll
        for (int c = 0; c < 3; c++) {
            uint32_t mb = smem_u32(&mbs[c]);
            MBAR_EXPECT(mb, 65536);
            bulk_g2s(sb + c * 65536,         xsrc + c * 32768, 32768, mb);
            bulk_g2s(sb + c * 65536 + 32768, wsrc + c * 32768, 32768, mb);
        }
    }

    int rowA = (l & 7) + ((l >> 3) & 1) * 8;
    int colA = (l >> 4) * 8;
    uint32_t mX = (uint32_t)((rowA & 7) << 4);

    float o[16][4];
#pragma unroll
    for (int i = 0; i < 16; i++)
#pragma unroll
        for (int j = 0; j < 4; j++) o[i][j] = 0.f;

    for (int ch = 0; ch < 4; ch++) {
        int bf = ch % 3;
        mbar_wait(smem_u32(&mbs[bf]), (ch >= 3) ? 1u : 0u);

        uint32_t sX = sb + bf * 65536;
        uint32_t sW = sX + 32768;
        uint32_t xh = sX + (uint32_t)((wid * 16 + rowA) * 128);
        uint32_t xl = xh + 16384;

#pragma unroll
        for (int ks = 0; ks < 4; ks++) {
            uint32_t aH[4], aL[4];
            uint32_t cbX = ((uint32_t)(colA * 2 + ks * 32)) ^ mX;
            ldsm4(aH, xh + cbX);
            ldsm4(aL, xl + cbX);
            uint32_t wrow = sW + (uint32_t)((rowA + ks * 16) * 256);
#pragma unroll
            for (int nb = 0; nb < 8; nb++) {
                uint32_t bh[4], bl[4];
                uint32_t cbW = ((uint32_t)(colA * 2 + nb * 32)) ^ mX;
                ldsm4t(bh, wrow + cbW);
                ldsm4t(bl, wrow + 16384 + cbW);
                mma16816(o[2 * nb],     aH, bh);
                mma16816(o[2 * nb],     aH, bl);
                mma16816(o[2 * nb],     aL, bh);
                mma16816(o[2 * nb + 1], aH, bh + 2);
                mma16816(o[2 * nb + 1], aH, bl + 2);
                mma16816(o[2 * nb + 1], aL, bh + 2);
            }
        }
        __syncthreads();            // buffer consumed by all warps
        if (ch + 3 < 4 && t == 0) {
            uint32_t mb = smem_u32(&mbs[bf]);
            MBAR_EXPECT(mb, 65536);
            bulk_g2s(sb + bf * 65536,         xsrc + (ch + 3) * 32768, 32768, mb);
            bulk_g2s(sb + bf * 65536 + 32768, wsrc + (ch + 3) * 32768, 32768, mb);
        }
    }

    // ---- epilogue: optional xpos rotation, split, store to Q/K/V images ----
    uint8_t* img = (mode == 0) ? g_Qi : (mode == 1) ? g_Ki : g_Vi;
    int bn = blockIdx.z >> 4;
    int tileg = bn * 64 + (blockIdx.z & 15) * 4 + (wid >> 1);
    int r5 = (wid & 1) * 16 + (l >> 2);
    uint32_t m5 = (uint32_t)(((l >> 2) & 7) << 4);
    uint8_t* tb = img + (size_t)(tileg * 2) * 16384;
    int s1 = (blockIdx.z & 15) * 128 + wid * 16 + (l >> 2);
    int s2 = s1 + 8;

#pragma unroll
    for (int nb = 0; nb < 16; nb++) {
        int col = nh * 128 + nb * 8 + 2 * (l & 3);
        float a0 = o[nb][0], a1 = o[nb][1];
        float b0 = o[nb][2], b1 = o[nb][3];
        if (mode != 2) {
            float4 t1 = g_tab[s1 * 128 + (col >> 1)];
            float4 t2 = g_tab[s2 * 128 + (col >> 1)];
            float sc1 = (mode == 0) ? t1.z : t1.w;
            float sc2 = (mode == 0) ? t2.z : t2.w;
            float sn1 = t1.x * sc1, cs1 = t1.y * sc1;
            float sn2 = t2.x * sc2, cs2 = t2.y * sc2;
            float n0 = a0 * cs1 - a1 * sn1;
            float n1 = a1 * cs1 + a0 * sn1;
            float m0 = b0 * cs2 - b1 * sn2;
            float m1 = b1 * cs2 + b0 * sn2;
            a0 = n0; a1 = n1; b0 = m0; b1 = m1;
        }
        uint32_t h1, l1, h2, l2;
        split2(a0, a1, h1, l1);
        split2(b0, b1, h2, l2);
        uint32_t offc = ((uint32_t)(col * 2)) ^ m5;
        *(uint32_t*)(tb + r5 * 512 + offc)              = h1;
        *(uint32_t*)(tb + 16384 + r5 * 512 + offc)      = l1;
        *(uint32_t*)(tb + (r5 + 8) * 512 + offc)        = h2;
        *(uint32_t*)(tb + 16384 + (r5 + 8) * 512 + offc) = l2;
    }
}

// ---------------------------------------------------------------------------
// Raw mma.sync retention attention, TMA-bulk staged, windowed (d <= ~256+).
// smem: Q images 128KB resident + K 32KB + V 32KB = 192KB, 1 CTA/SM.
// ---------------------------------------------------------------------------
#define ATTN_SMEM 196608

__global__ void __launch_bounds__(256, 1) attn_kernel(float* __restrict__ out) {
    extern __shared__ __align__(128) uint8_t sma[];
    __shared__ __align__(8) uint64_t mba[3];
    uint32_t sb = smem_u32(sma);
    int t = threadIdx.x, wid = t >> 5, l = t & 31;

    int qt = 15 - (blockIdx.x >> 4);   // heavy q-tiles first
    int bn = blockIdx.x & 15;
    int jlo = max(0, qt * 4 - 8);      // drop d >= 257 (xpos damps further)
    int jhi = qt * 4 + 3;

    if (t == 0) {
#pragma unroll
        for (int i = 0; i < 3; i++) MBAR_INIT(smem_u32(&mba[i]), 1);
    }
    __syncthreads();
    uint32_t mbQ = smem_u32(&mba[0]);
    uint32_t mbK = smem_u32(&mba[1]);
    uint32_t mbV = smem_u32(&mba[2]);

    const uint8_t* qsrc = g_Qi + (size_t)((bn * 64 + qt * 4) * 2) * 16384;
    const uint8_t* ksrc = g_Ki + (size_t)(bn * 64 * 2) * 16384;
    const uint8_t* vsrc = g_Vi + (size_t)(bn * 64 * 2) * 16384;

    if (t == 0) {
        MBAR_EXPECT(mbQ, 131072);
        bulk_g2s(sb, qsrc, 131072, mbQ);
        MBAR_EXPECT(mbK, 32768);
        bulk_g2s(sb + 131072, ksrc + (size_t)jlo * 32768, 32768, mbK);
        MBAR_EXPECT(mbV, 32768);
        bulk_g2s(sb + 163840, vsrc + (size_t)jlo * 32768, 32768, mbV);
    }

    int rowA = (l & 7) + ((l >> 3) & 1) * 8;
    int colA = (l >> 4) * 8;
    int rowK = (l & 7) + ((l >> 4) & 1) * 8;
    int colK = ((l >> 3) & 1) * 8;
    uint32_t mA = (uint32_t)((rowA & 7) << 4);
    uint32_t mK = (uint32_t)((rowK & 7) << 4);

    uint32_t qh = sb + (uint32_t)((wid >> 1) * 32768 + ((wid & 1) * 16 + rowA) * 512);
    uint32_t ql = qh + 16384;
    uint32_t kh = sb + 131072 + (uint32_t)(rowK * 512);
    uint32_t kl = kh + 16384;
    uint32_t vh = sb + 163840 + (uint32_t)(rowA * 512);
    uint32_t vl = vh + 16384;

    float o[32][4];
#pragma unroll
    for (int i = 0; i < 32; i++)
#pragma unroll
        for (int j = 0; j < 4; j++) o[i][j] = 0.f;

    mbar_wait(mbQ, 0);
    uint32_t phk = 0, phv = 0;
    int r0g = qt * 128 + wid * 16 + (l >> 2);

    for (int kt = jlo; kt <= jhi; kt++) {
        int j0 = kt * 32;
        mbar_wait(mbK, phk); phk ^= 1;

        // ---- S = Q K^T (split-3), S in registers ----
        float sa[4][4];
#pragma unroll
        for (int i = 0; i < 4; i++)
#pragma unroll
            for (int j = 0; j < 4; j++) sa[i][j] = 0.f;

#pragma unroll 4
        for (int kc = 0; kc < 16; kc++) {
            uint32_t aH[4], aL[4], bh[8], bl[8];
            uint32_t cbq = ((uint32_t)(colA * 2 + kc * 32)) ^ mA;
            uint32_t cbk = ((uint32_t)(colK * 2 + kc * 32)) ^ mK;
            ldsm4(aH, qh + cbq);
            ldsm4(aL, ql + cbq);
            ldsm4(bh,     kh + cbk);
            ldsm4(bh + 4, kh + 8192 + cbk);
            ldsm4(bl,     kl + cbk);
            ldsm4(bl + 4, kl + 8192 + cbk);
#pragma unroll
            for (int tt = 0; tt < 4; tt++) {
                mma16816(sa[tt], aH, bh + tt * 2);
                mma16816(sa[tt], aH, bl + tt * 2);
                mma16816(sa[tt], aL, bh + tt * 2);
            }
        }
        __syncthreads();                       // K consumed by all warps
        if (kt < jhi && t == 0) {
            MBAR_EXPECT(mbK, 32768);
            bulk_g2s(sb + 131072, ksrc + (size_t)(kt + 1) * 32768, 32768, mbK);
        }

        // ---- decay + causal mask + bf16 split, in registers ----
        uint32_t pH[2][4], pL[2][4];
#pragma unroll
        for (int tt = 0; tt < 4; tt++) {
            int c0 = j0 + tt * 8 + 2 * (l & 3);
            int d = r0g - c0;
            float e0 = exp2f((float)d * L2G);
            float e8 = e0 * G8C;
            float p0 = (d >= 0)  ? sa[tt][0] * e0 : 0.f;
            float p1 = (d >= 1)  ? sa[tt][1] * (e0 * IGAM) : 0.f;
            float p2 = (d >= -8) ? sa[tt][2] * e8 : 0.f;
            float p3 = (d >= -7) ? sa[tt][3] * (e8 * IGAM) : 0.f;
            uint32_t h01, l01, h23, l23;
            split2(p0, p1, h01, l01);
            split2(p2, p3, h23, l23);
            int c2 = tt >> 1, jj = tt & 1;
            pH[c2][2 * jj + 0] = h01;  pH[c2][2 * jj + 1] = h23;
            pL[c2][2 * jj + 0] = l01;  pL[c2][2 * jj + 1] = l23;
        }

        mbar_wait(mbV, phv); phv ^= 1;

        // ---- O += P V (split-3) ----
#pragma unroll
        for (int c2 = 0; c2 < 2; c2++) {
#pragma unroll
            for (int nb = 0; nb < 16; nb++) {
                uint32_t bh[4], bl[4];
                uint32_t cbv = ((uint32_t)(colA * 2 + nb * 32)) ^ mA;
                ldsm4t(bh, vh + c2 * 8192 + cbv);
                ldsm4t(bl, vl + c2 * 8192 + cbv);
                mma16816(o[2 * nb],     pH[c2], bh);
                mma16816(o[2 * nb],     pH[c2], bl);
                mma16816(o[2 * nb],     pL[c2], bh);
                mma16816(o[2 * nb + 1], pH[c2], bh + 2);
                mma16816(o[2 * nb + 1], pH[c2], bl + 2);
                mma16816(o[2 * nb + 1], pL[c2], bh + 2);
            }
        }
        __syncthreads();                       // V consumed
        if (kt < jhi && t == 0) {
            MBAR_EXPECT(mbV, 32768);
            bulk_g2s(sb + 163840, vsrc + (size_t)(kt + 1) * 32768, 32768, mbV);
        }
    }

    float* ob = out + ((size_t)bn * S_LEN + r0g) * HID + 2 * (l & 3);
#pragma unroll
    for (int tt = 0; tt < 32; tt++) {
        *(float2*)(ob + tt * 8)           = make_float2(o[tt][0], o[tt][1]);
        *(float2*)(ob + 8 * HID + tt * 8) = make_float2(o[tt][2], o[tt][3]);
    }
}

// ---------------------------------------------------------------------------
extern "C" void kernel_launch(void* const* d_in, const int* in_sizes, int n_in,
                              void* d_out, int out_size) {
    const float* X  = (const float*)d_in[0];
    const float* Wq = (const float*)d_in[1];
    const float* Wk = (const float*)d_in[2];
    const float* Wv = (const float*)d_in[3];
    float* out = (float*)d_out;

    prep_kernel<<<9600, 256>>>(X, Wq, Wk, Wv);

    cudaFuncSetAttribute(proj_kernel, cudaFuncAttributeMaxDynamicSharedMemorySize, PROJ_SMEM);
    proj_kernel<<<dim3(2, 3, 256), 256, PROJ_SMEM>>>();

    cudaFuncSetAttribute(attn_kernel, cudaFuncAttributeMaxDynamicSharedMemorySize, ATTN_SMEM);
    attn_kernel<<<16 * BN, 256, ATTN_SMEM>>>(out);
}